// round 2
// baseline (speedup 1.0000x reference)
#include <cuda_runtime.h>
#include <math.h>

// ---------------- problem constants ----------------
#define BATCH  2
#define SEQ    2048
#define DMODEL 5120
#define NH     8
#define DHEAD  640
#define DROPE  16
#define SPLITD 624
#define DKV    128
#define BS     (BATCH*SEQ)            // 4096 rows
#define NBASE  (NH*SPLITD)            // 4992
#define NFULL  (NH*DHEAD)             // 5120

// ---------------- scratch (device globals; no allocations allowed) ----------
__device__ __align__(128) float g_ckv  [BS*DKV];
__device__ __align__(128) float g_cq   [BS*DKV];
__device__ __align__(128) float g_qbase[(long)BS*NBASE];
__device__ __align__(128) float g_kbase[(long)BS*NBASE];
__device__ __align__(128) float g_qrot [BS*NH*DROPE];
__device__ __align__(128) float g_krot [BS*NH*DROPE];
__device__ __align__(128) float g_q    [(long)BS*NFULL];
__device__ __align__(128) float g_k    [(long)BS*NFULL];
__device__ __align__(128) float g_v    [(long)BS*NFULL];
__device__ __align__(128) float g_sc   [(long)BATCH*NH*SEQ*SEQ];
__device__ __align__(128) float g_ao   [(long)BS*NFULL];

// ---------------- generic strided/batched SGEMM (NN) -------------------------
// C[m,n] = scale * sum_k A[m*lda+k]*B[k*ldb+n] + bias[n]
// Requires M%128==0, N%128==0, K%8==0 (all shapes here satisfy this).
__global__ void __launch_bounds__(256) gemm_nn(
    int M, int N, int K,
    const float* __restrict__ A, int lda, long offA_b, long offA_h,
    const float* __restrict__ B, int ldb, long offB_b, long offB_h,
    float* __restrict__ C, int ldc, long offC_b, long offC_h,
    const float* __restrict__ bias, float scale, int nh)
{
    const int z  = blockIdx.z;
    const int bz = z / nh, hz = z - bz*nh;
    A += (long)bz*offA_b + (long)hz*offA_h;
    B += (long)bz*offB_b + (long)hz*offB_h;
    C += (long)bz*offC_b + (long)hz*offC_h;

    __shared__ float As[8][128];
    __shared__ float Bs[8][128];

    const int tid  = threadIdx.x;
    const int ty   = tid >> 4, tx = tid & 15;
    const int mBase = blockIdx.y * 128, nBase = blockIdx.x * 128;

    const int aRow = tid >> 1,  aCol = (tid & 1) * 4;    // 128x8 A tile
    const int bRow = tid >> 5,  bCol = (tid & 31) * 4;   // 8x128 B tile

    const float* Aptr = A + (long)(mBase + aRow)*lda + aCol;
    const float* Bptr = B + (long)bRow*ldb + nBase + bCol;

    float acc[8][8];
    #pragma unroll
    for (int i = 0; i < 8; i++)
        #pragma unroll
        for (int j = 0; j < 8; j++) acc[i][j] = 0.f;

    for (int k0 = 0; k0 < K; k0 += 8) {
        float4 av = *(const float4*)Aptr;  Aptr += 8;
        As[aCol+0][aRow] = av.x; As[aCol+1][aRow] = av.y;
        As[aCol+2][aRow] = av.z; As[aCol+3][aRow] = av.w;
        float4 bv = *(const float4*)Bptr;  Bptr += 8*(long)ldb;
        *(float4*)&Bs[bRow][bCol] = bv;
        __syncthreads();

        #pragma unroll
        for (int kk = 0; kk < 8; kk++) {
            float ar[8], br[8];
            #pragma unroll
            for (int i = 0; i < 8; i++) ar[i] = As[kk][ty*8 + i];
            #pragma unroll
            for (int j = 0; j < 8; j++) br[j] = Bs[kk][tx*8 + j];
            #pragma unroll
            for (int i = 0; i < 8; i++)
                #pragma unroll
                for (int j = 0; j < 8; j++) acc[i][j] += ar[i]*br[j];
        }
        __syncthreads();
    }

    #pragma unroll
    for (int i = 0; i < 8; i++) {
        float* cp = C + (long)(mBase + ty*8 + i)*ldc + nBase + tx*8;
        #pragma unroll
        for (int j = 0; j < 8; j += 4) {
            float4 o;
            o.x = acc[i][j+0]*scale; o.y = acc[i][j+1]*scale;
            o.z = acc[i][j+2]*scale; o.w = acc[i][j+3]*scale;
            if (bias) {
                const float* bp = bias + nBase + tx*8 + j;
                o.x += bp[0]; o.y += bp[1]; o.z += bp[2]; o.w += bp[3];
            }
            *(float4*)(cp + j) = o;
        }
    }
}

// ---------------- generic strided/batched SGEMM (NT) -------------------------
// C[m,n] = scale * sum_k A[m*lda+k]*B[n*ldb+k]
__global__ void __launch_bounds__(256) gemm_nt(
    int M, int N, int K,
    const float* __restrict__ A, int lda, long offA_b, long offA_h,
    const float* __restrict__ B, int ldb, long offB_b, long offB_h,
    float* __restrict__ C, int ldc, long offC_b, long offC_h,
    float scale, int nh)
{
    const int z  = blockIdx.z;
    const int bz = z / nh, hz = z - bz*nh;
    A += (long)bz*offA_b + (long)hz*offA_h;
    B += (long)bz*offB_b + (long)hz*offB_h;
    C += (long)bz*offC_b + (long)hz*offC_h;

    __shared__ float As[8][128];
    __shared__ float Bs[8][128];

    const int tid  = threadIdx.x;
    const int ty   = tid >> 4, tx = tid & 15;
    const int mBase = blockIdx.y * 128, nBase = blockIdx.x * 128;

    const int aRow = tid >> 1, aCol = (tid & 1) * 4;   // 128 rows x 8 k
    const float* Aptr = A + (long)(mBase + aRow)*lda + aCol;
    const float* Bptr = B + (long)(nBase + aRow)*ldb + aCol;  // same tiling for B^T

    float acc[8][8];
    #pragma unroll
    for (int i = 0; i < 8; i++)
        #pragma unroll
        for (int j = 0; j < 8; j++) acc[i][j] = 0.f;

    for (int k0 = 0; k0 < K; k0 += 8) {
        float4 av = *(const float4*)Aptr;  Aptr += 8;
        As[aCol+0][aRow] = av.x; As[aCol+1][aRow] = av.y;
        As[aCol+2][aRow] = av.z; As[aCol+3][aRow] = av.w;
        float4 bv = *(const float4*)Bptr;  Bptr += 8;
        Bs[aCol+0][aRow] = bv.x; Bs[aCol+1][aRow] = bv.y;
        Bs[aCol+2][aRow] = bv.z; Bs[aCol+3][aRow] = bv.w;
        __syncthreads();

        #pragma unroll
        for (int kk = 0; kk < 8; kk++) {
            float ar[8], br[8];
            #pragma unroll
            for (int i = 0; i < 8; i++) ar[i] = As[kk][ty*8 + i];
            #pragma unroll
            for (int j = 0; j < 8; j++) br[j] = Bs[kk][tx*8 + j];
            #pragma unroll
            for (int i = 0; i < 8; i++)
                #pragma unroll
                for (int j = 0; j < 8; j++) acc[i][j] += ar[i]*br[j];
        }
        __syncthreads();
    }

    #pragma unroll
    for (int i = 0; i < 8; i++) {
        float* cp = C + (long)(mBase + ty*8 + i)*ldc + nBase + tx*8;
        #pragma unroll
        for (int j = 0; j < 8; j += 4) {
            float4 o;
            o.x = acc[i][j+0]*scale; o.y = acc[i][j+1]*scale;
            o.z = acc[i][j+2]*scale; o.w = acc[i][j+3]*scale;
            *(float4*)(cp + j) = o;
        }
    }
}

// ---------------- pack q/k (concat base + rotated rope) ----------------------
// inv_freq = [1, 0.1, 0.01, 0.001] exactly (10000^0.25 == 10).
// Only the first 8 of the 16 rope dims rotate (cos has 8 cols); dims 8..15 pass through.
__global__ void __launch_bounds__(256) pack_rope(
    const float* __restrict__ qbase, const float* __restrict__ qrot,
    const float* __restrict__ kbase, const float* __restrict__ krot,
    float* __restrict__ q, float* __restrict__ k)
{
    long idx = (long)blockIdx.x * blockDim.x + threadIdx.x;
    const long total = (long)BS * NH * DHEAD;
    if (idx >= total) return;
    int d  = (int)(idx % DHEAD);
    int hh = (int)((idx / DHEAD) % NH);
    long bs = idx / ((long)DHEAD * NH);
    float qv, kv;
    if (d < SPLITD) {
        qv = qbase[bs*NBASE + hh*SPLITD + d];
        kv = kbase[bs*NBASE + hh*SPLITD + d];
    } else {
        int i = d - SPLITD;   // 0..15
        const float* qr = qrot + bs*(NH*DROPE) + hh*DROPE;
        const float* kr = krot + bs*(NH*DROPE) + hh*DROPE;
        if (i < 8) {
            int s = (int)(bs % SEQ);
            int j = i & 3;
            float invf = (j == 0) ? 1.f : (j == 1) ? 0.1f : (j == 2) ? 0.01f : 0.001f;
            float ang = ((float)s / 40.0f) * invf;
            float c = cosf(ang), sn = sinf(ang);
            if (i < 4) { qv = qr[i]*c - qr[i+4]*sn;  kv = kr[i]*c - kr[i+4]*sn; }
            else       { qv = qr[i]*c + qr[i-4]*sn;  kv = kr[i]*c + kr[i-4]*sn; }
        } else {
            qv = qr[i]; kv = kr[i];
        }
    }
    q[idx] = qv; k[idx] = kv;
}

// ---------------- one-pass register softmax over rows of length 2048 ---------
__device__ __forceinline__ float warpMax(float v){
    #pragma unroll
    for (int o = 16; o; o >>= 1) v = fmaxf(v, __shfl_xor_sync(0xffffffffu, v, o));
    return v;
}
__device__ __forceinline__ float warpSum(float v){
    #pragma unroll
    for (int o = 16; o; o >>= 1) v += __shfl_xor_sync(0xffffffffu, v, o);
    return v;
}

__global__ void __launch_bounds__(256) softmax_rows(float* __restrict__ sc)
{
    float* row = sc + (long)blockIdx.x * SEQ;
    const int t = threadIdx.x;
    float4 a = *(float4*)(row + 4*t);
    float4 b = *(float4*)(row + 1024 + 4*t);

    float m = fmaxf(fmaxf(fmaxf(a.x, a.y), fmaxf(a.z, a.w)),
                    fmaxf(fmaxf(b.x, b.y), fmaxf(b.z, b.w)));
    __shared__ float sm[8], ss[8];
    float wm = warpMax(m);
    if ((t & 31) == 0) sm[t >> 5] = wm;
    __syncthreads();
    if (t < 32) { float x = (t < 8) ? sm[t] : -INFINITY; x = warpMax(x); if (t == 0) sm[0] = x; }
    __syncthreads();
    const float bm = sm[0];

    a.x = __expf(a.x - bm); a.y = __expf(a.y - bm); a.z = __expf(a.z - bm); a.w = __expf(a.w - bm);
    b.x = __expf(b.x - bm); b.y = __expf(b.y - bm); b.z = __expf(b.z - bm); b.w = __expf(b.w - bm);
    float s = a.x + a.y + a.z + a.w + b.x + b.y + b.z + b.w;
    float wsu = warpSum(s);
    if ((t & 31) == 0) ss[t >> 5] = wsu;
    __syncthreads();
    if (t < 32) { float x = (t < 8) ? ss[t] : 0.f; x = warpSum(x); if (t == 0) ss[0] = x; }
    __syncthreads();
    const float inv = 1.f / ss[0];

    a.x *= inv; a.y *= inv; a.z *= inv; a.w *= inv;
    b.x *= inv; b.y *= inv; b.z *= inv; b.w *= inv;
    *(float4*)(row + 4*t) = a;
    *(float4*)(row + 1024 + 4*t) = b;
}

// ---------------- launch ------------------------------------------------------
extern "C" void kernel_launch(void* const* d_in, const int* in_sizes, int n_in,
                              void* d_out, int out_size)
{
    const float* h     = (const float*)d_in[0];
    const float* W_dkv = (const float*)d_in[1];
    const float* b_dkv = (const float*)d_in[2];
    const float* W_dq  = (const float*)d_in[3];
    const float* b_dq  = (const float*)d_in[4];
    const float* W_uk  = (const float*)d_in[5];
    const float* b_uk  = (const float*)d_in[6];
    const float* W_uv  = (const float*)d_in[7];
    const float* b_uv  = (const float*)d_in[8];
    const float* W_uq  = (const float*)d_in[9];
    const float* b_uq  = (const float*)d_in[10];
    const float* W_qr  = (const float*)d_in[11];
    const float* b_qr  = (const float*)d_in[12];
    const float* W_kr  = (const float*)d_in[13];
    const float* b_kr  = (const float*)d_in[14];
    const float* W_o   = (const float*)d_in[15];
    const float* b_o   = (const float*)d_in[16];
    float* out = (float*)d_out;

    float *ckv, *cq, *qb, *kb, *qr, *kr, *q, *k, *v, *sc, *ao;
    cudaGetSymbolAddress((void**)&ckv, g_ckv);
    cudaGetSymbolAddress((void**)&cq,  g_cq);
    cudaGetSymbolAddress((void**)&qb,  g_qbase);
    cudaGetSymbolAddress((void**)&kb,  g_kbase);
    cudaGetSymbolAddress((void**)&qr,  g_qrot);
    cudaGetSymbolAddress((void**)&kr,  g_krot);
    cudaGetSymbolAddress((void**)&q,   g_q);
    cudaGetSymbolAddress((void**)&k,   g_k);
    cudaGetSymbolAddress((void**)&v,   g_v);
    cudaGetSymbolAddress((void**)&sc,  g_sc);
    cudaGetSymbolAddress((void**)&ao,  g_ao);

    const dim3 T(256);
    const long SS  = (long)SEQ * SEQ;
    const long ROW = (long)SEQ * NFULL;     // per-batch stride of (S, H*D) tensors

    // 1-3: down-projections from h (K=5120, N=128)
    gemm_nn<<<dim3(1, BS/128, 1), T>>>(BS, DKV, DMODEL, h, DMODEL, 0, 0,
                                       W_dkv, DKV, 0, 0, ckv, DKV, 0, 0, b_dkv, 1.f, 1);
    gemm_nn<<<dim3(1, BS/128, 1), T>>>(BS, DKV, DMODEL, h, DMODEL, 0, 0,
                                       W_dq, DKV, 0, 0, cq, DKV, 0, 0, b_dq, 1.f, 1);
    gemm_nn<<<dim3(1, BS/128, 1), T>>>(BS, NH*DROPE, DMODEL, h, DMODEL, 0, 0,
                                       W_kr, NH*DROPE, 0, 0, kr, NH*DROPE, 0, 0, b_kr, 1.f, 1);

    // 4-7: up-projections (K=128)
    gemm_nn<<<dim3(NBASE/128, BS/128, 1), T>>>(BS, NBASE, DKV, ckv, DKV, 0, 0,
                                       W_uk, NBASE, 0, 0, kb, NBASE, 0, 0, b_uk, 1.f, 1);
    gemm_nn<<<dim3(NFULL/128, BS/128, 1), T>>>(BS, NFULL, DKV, ckv, DKV, 0, 0,
                                       W_uv, NFULL, 0, 0, v, NFULL, 0, 0, b_uv, 1.f, 1);
    gemm_nn<<<dim3(NBASE/128, BS/128, 1), T>>>(BS, NBASE, DKV, cq, DKV, 0, 0,
                                       W_uq, NBASE, 0, 0, qb, NBASE, 0, 0, b_uq, 1.f, 1);
    gemm_nn<<<dim3(1, BS/128, 1), T>>>(BS, NH*DROPE, DKV, cq, DKV, 0, 0,
                                       W_qr, NH*DROPE, 0, 0, qr, NH*DROPE, 0, 0, b_qr, 1.f, 1);

    // 8: pack q/k + RoPE
    {
        long total = (long)BS * NH * DHEAD;
        int blocks = (int)((total + 255) / 256);
        pack_rope<<<blocks, T>>>(qb, qr, kb, kr, q, k);
    }

    // 9: scores = q @ k^T / sqrt(D_HEAD), batched over B*H
    const float scScale = 1.f / sqrtf((float)DHEAD);
    gemm_nt<<<dim3(SEQ/128, SEQ/128, BATCH*NH), T>>>(SEQ, SEQ, DHEAD,
        q, NFULL, ROW, DHEAD,
        k, NFULL, ROW, DHEAD,
        sc, SEQ, (long)NH*SS, SS,
        scScale, NH);

    // 10: softmax over last dim
    softmax_rows<<<BATCH*NH*SEQ, T>>>(sc);

    // 11: attn @ v, batched over B*H
    gemm_nn<<<dim3(DHEAD/128, SEQ/128, BATCH*NH), T>>>(SEQ, DHEAD, SEQ,
        sc, SEQ, (long)NH*SS, SS,
        v, NFULL, ROW, DHEAD,
        ao, NFULL, ROW, DHEAD,
        (const float*)nullptr, 1.f, NH);

    // 12: final projection
    gemm_nn<<<dim3(DMODEL/128, BS/128, 1), T>>>(BS, DMODEL, DMODEL,
        ao, DMODEL, 0, 0, W_o, DMODEL, 0, 0, out, DMODEL, 0, 0, b_o, 1.f, 1);
}

// round 6
// speedup vs baseline: 3.2541x; 3.2541x over previous
#include <cuda_runtime.h>
#include <cstdint>
#include <math.h>

// ---------------- problem constants ----------------
#define BATCH  2
#define SEQ    2048
#define DMODEL 5120
#define NH     8
#define DHEAD  640
#define DROPE  16
#define SPLITD 624
#define DKV    128
#define BS     (BATCH*SEQ)            // 4096 rows
#define NBASE  (NH*SPLITD)            // 4992
#define NFULL  (NH*DHEAD)             // 5120

// ---------------- scratch (device globals; no allocations allowed) ----------
__device__ __align__(128) float g_ckv  [BS*DKV];
__device__ __align__(128) float g_cq   [BS*DKV];
__device__ __align__(128) float g_qbase[(long)BS*NBASE];
__device__ __align__(128) float g_kbase[(long)BS*NBASE];
__device__ __align__(128) float g_qrot [BS*NH*DROPE];
__device__ __align__(128) float g_krot [BS*NH*DROPE];
__device__ __align__(128) float g_q    [(long)BS*NFULL];
__device__ __align__(128) float g_k    [(long)BS*NFULL];
__device__ __align__(128) float g_v    [(long)BS*NFULL];
__device__ __align__(128) float g_vT   [(long)BS*NFULL];
__device__ __align__(128) float g_sc   [(long)BATCH*NH*SEQ*SEQ];
__device__ __align__(128) float g_ao   [(long)BS*NFULL];
// transposed weights ([N,K] K-major for NT GEMM)
__device__ __align__(128) float g_wdkvT[DKV*DMODEL];
__device__ __align__(128) float g_wdqT [DKV*DMODEL];
__device__ __align__(128) float g_wkrT [NH*DROPE*DMODEL];
__device__ __align__(128) float g_wukT [(long)NBASE*DKV];
__device__ __align__(128) float g_wuvT [(long)NFULL*DKV];
__device__ __align__(128) float g_wuqT [(long)NBASE*DKV];
__device__ __align__(128) float g_wqrT [NH*DROPE*DKV];
__device__ __align__(128) float g_woT  [(long)DMODEL*DMODEL];

// ---------------- tf32 helpers (portable PTX, no 'a' features) --------------
__device__ __forceinline__ uint32_t tf32r(float x) {
    uint32_t r;
    asm("cvt.rna.tf32.f32 %0, %1;" : "=r"(r) : "f"(x));
    return r;
}

#define MMA_TF32(c, a, b) \
    asm volatile("mma.sync.aligned.m16n8k8.row.col.f32.tf32.tf32.f32 " \
        "{%0,%1,%2,%3}, {%4,%5,%6,%7}, {%8,%9}, {%0,%1,%2,%3};" \
        : "+f"((c)[0]), "+f"((c)[1]), "+f"((c)[2]), "+f"((c)[3]) \
        : "r"((a)[0]), "r"((a)[1]), "r"((a)[2]), "r"((a)[3]), \
          "r"((b)[0]), "r"((b)[1]))

// =================== tf32 mma.sync NT GEMM ===================
// C[m,n] = scale * sum_k A[m*lda+k] * B[n*ldb+k] (+ bias[n])
// M%128==0, N%128==0, K%32==0.
// CTA: 128x128 tile, 256 threads (8 warps, 4M x 2N), warp tile 32x64.
#define SAK   36                      // smem row stride (floats): (4*row+k)%32 conflict-free
#define STG_F (128*SAK)               // floats per operand per stage (4608)
#define GEMM_SMEM (2*2*STG_F*4)       // 73728 bytes

__global__ void __launch_bounds__(256) gemm_mma(
    int M, int N, int K,
    const float* __restrict__ A, int lda, long offA_b, long offA_h,
    const float* __restrict__ B, int ldb, long offB_b, long offB_h,
    float* __restrict__ C, int ldc, long offC_b, long offC_h,
    const float* __restrict__ bias, float scale, int nh)
{
    extern __shared__ float sm[];
    const int tid  = threadIdx.x;
    const int wid  = tid >> 5, lane = tid & 31;
    const int g    = lane >> 2, tq = lane & 3;
    const int warpM = wid >> 1, warpN = wid & 1;

    const int z  = blockIdx.z;
    const int bz = z / nh, hz = z - bz*nh;
    A += (long)bz*offA_b + (long)hz*offA_h;
    B += (long)bz*offB_b + (long)hz*offB_h;
    C += (long)bz*offC_b + (long)hz*offC_h;

    const int mBase = blockIdx.y * 128;
    const int nBase = blockIdx.x * 128;
    const float* Ag = A + (long)mBase*lda;
    const float* Bg = B + (long)nBase*ldb;

    // per-thread gmem->smem mapping: 4 float4 per operand per stage
    int arow[4], acol[4];
    #pragma unroll
    for (int i = 0; i < 4; i++) {
        int f = i*256 + tid;
        arow[i] = f >> 3;
        acol[i] = (f & 7) << 2;
    }

    float acc[2][8][4];
    #pragma unroll
    for (int mt = 0; mt < 2; mt++)
        #pragma unroll
        for (int nt = 0; nt < 8; nt++)
            #pragma unroll
            for (int r = 0; r < 4; r++) acc[mt][nt][r] = 0.f;

    const int T = K / 32;
    float4 rA[4], rB[4];

#define LOADR(t) do { \
    const float* _Ak = Ag + (t)*32; const float* _Bk = Bg + (t)*32; \
    _Pragma("unroll") \
    for (int i = 0; i < 4; i++) { \
        rA[i] = *(const float4*)(_Ak + (long)arow[i]*lda + acol[i]); \
        rB[i] = *(const float4*)(_Bk + (long)arow[i]*ldb + acol[i]); \
    } } while (0)

#define STORES(buf) do { \
    float* _As = sm + (buf)*(2*STG_F); float* _Bs = _As + STG_F; \
    _Pragma("unroll") \
    for (int i = 0; i < 4; i++) { \
        int _b = arow[i]*SAK + acol[i]; \
        float4 _ta, _tb; \
        _ta.x = __uint_as_float(tf32r(rA[i].x)); _ta.y = __uint_as_float(tf32r(rA[i].y)); \
        _ta.z = __uint_as_float(tf32r(rA[i].z)); _ta.w = __uint_as_float(tf32r(rA[i].w)); \
        _tb.x = __uint_as_float(tf32r(rB[i].x)); _tb.y = __uint_as_float(tf32r(rB[i].y)); \
        _tb.z = __uint_as_float(tf32r(rB[i].z)); _tb.w = __uint_as_float(tf32r(rB[i].w)); \
        *(float4*)(_As + _b) = _ta; \
        *(float4*)(_Bs + _b) = _tb; \
    } } while (0)

    // prologue
    LOADR(0);
    STORES(0);
    if (T > 1) LOADR(1);

    for (int t = 0; t < T; ++t) {
        __syncthreads();
        if (t + 1 < T) STORES((t+1) & 1);
        if (t + 2 < T) LOADR(t+2);

        const float* As = sm + (t & 1)*(2*STG_F);
        const float* Bs = As + STG_F;
        #pragma unroll
        for (int ks = 0; ks < 4; ks++) {
            const int k0 = ks << 3;
            uint32_t afr[2][4], bfr[8][2];
            #pragma unroll
            for (int mt = 0; mt < 2; mt++) {
                const int m = warpM*32 + mt*16 + g;
                afr[mt][0] = __float_as_uint(As[(m    )*SAK + k0 + tq    ]);
                afr[mt][1] = __float_as_uint(As[(m + 8)*SAK + k0 + tq    ]);
                afr[mt][2] = __float_as_uint(As[(m    )*SAK + k0 + tq + 4]);
                afr[mt][3] = __float_as_uint(As[(m + 8)*SAK + k0 + tq + 4]);
            }
            #pragma unroll
            for (int nt = 0; nt < 8; nt++) {
                const int n = warpN*64 + nt*8 + g;
                bfr[nt][0] = __float_as_uint(Bs[n*SAK + k0 + tq    ]);
                bfr[nt][1] = __float_as_uint(Bs[n*SAK + k0 + tq + 4]);
            }
            #pragma unroll
            for (int mt = 0; mt < 2; mt++)
                #pragma unroll
                for (int nt = 0; nt < 8; nt++)
                    MMA_TF32(acc[mt][nt], afr[mt], bfr[nt]);
        }
    }

    // epilogue
    #pragma unroll
    for (int mt = 0; mt < 2; mt++) {
        const int m0 = mBase + warpM*32 + mt*16 + g;
        #pragma unroll
        for (int nt = 0; nt < 8; nt++) {
            const int nc = nBase + warpN*64 + nt*8 + 2*tq;
            float2 lo, hi;
            lo.x = acc[mt][nt][0]*scale; lo.y = acc[mt][nt][1]*scale;
            hi.x = acc[mt][nt][2]*scale; hi.y = acc[mt][nt][3]*scale;
            if (bias) {
                float bx = bias[nc], by = bias[nc+1];
                lo.x += bx; lo.y += by; hi.x += bx; hi.y += by;
            }
            *(float2*)(C + (long)m0*ldc + nc)       = lo;
            *(float2*)(C + (long)(m0 + 8)*ldc + nc) = hi;
        }
    }
#undef LOADR
#undef STORES
}

// =================== transpose kernels ===================
__global__ void __launch_bounds__(256) transpose_w(
    const float* __restrict__ in, int ldin,
    float* __restrict__ out, int ldout, int R, int Ccols)
{
    __shared__ float tile[32][33];
    const int tx = threadIdx.x & 31, ty = threadIdx.x >> 5;
    const int bx = blockIdx.x * 32, by = blockIdx.y * 32;
    #pragma unroll
    for (int j = ty; j < 32; j += 8) {
        int r = by + j, c = bx + tx;
        if (r < R && c < Ccols) tile[j][tx] = in[(long)r*ldin + c];
    }
    __syncthreads();
    #pragma unroll
    for (int j = ty; j < 32; j += 8) {
        int r = bx + j, c = by + tx;
        if (r < Ccols && c < R) out[(long)r*ldout + c] = tile[tx][j];
    }
}

// v[b, s, h*640+d] -> vT[(b*NH+h), d, s]
__global__ void __launch_bounds__(256) transpose_v(
    const float* __restrict__ v, float* __restrict__ vT)
{
    __shared__ float tile[32][33];
    const int z = blockIdx.z;
    const int b = z >> 3, h = z & 7;
    const float* in = v + (long)b*SEQ*NFULL + h*DHEAD;
    float* out = vT + (long)z*DHEAD*SEQ;
    const int tx = threadIdx.x & 31, ty = threadIdx.x >> 5;
    const int bx = blockIdx.x * 32;   // d
    const int by = blockIdx.y * 32;   // s
    #pragma unroll
    for (int j = ty; j < 32; j += 8) {
        tile[j][tx] = in[(long)(by + j)*NFULL + bx + tx];
    }
    __syncthreads();
    #pragma unroll
    for (int j = ty; j < 32; j += 8) {
        out[(long)(bx + j)*SEQ + by + tx] = tile[tx][j];
    }
}

// ---------------- pack q/k (concat base + rotated rope) ----------------------
__global__ void __launch_bounds__(256) pack_rope(
    const float* __restrict__ qbase, const float* __restrict__ qrot,
    const float* __restrict__ kbase, const float* __restrict__ krot,
    float* __restrict__ q, float* __restrict__ k)
{
    long idx = (long)blockIdx.x * blockDim.x + threadIdx.x;
    const long total = (long)BS * NH * DHEAD;
    if (idx >= total) return;
    int d  = (int)(idx % DHEAD);
    int hh = (int)((idx / DHEAD) % NH);
    long bs = idx / ((long)DHEAD * NH);
    float qv, kv;
    if (d < SPLITD) {
        qv = qbase[bs*NBASE + hh*SPLITD + d];
        kv = kbase[bs*NBASE + hh*SPLITD + d];
    } else {
        int i = d - SPLITD;   // 0..15
        const float* qr = qrot + bs*(NH*DROPE) + hh*DROPE;
        const float* kr = krot + bs*(NH*DROPE) + hh*DROPE;
        if (i < 8) {
            int s = (int)(bs % SEQ);
            int j = i & 3;
            float invf = (j == 0) ? 1.f : (j == 1) ? 0.1f : (j == 2) ? 0.01f : 0.001f;
            float ang = ((float)s / 40.0f) * invf;
            float c = cosf(ang), sn = sinf(ang);
            if (i < 4) { qv = qr[i]*c - qr[i+4]*sn;  kv = kr[i]*c - kr[i+4]*sn; }
            else       { qv = qr[i]*c + qr[i-4]*sn;  kv = kr[i]*c + kr[i-4]*sn; }
        } else {
            qv = qr[i]; kv = kr[i];
        }
    }
    q[idx] = qv; k[idx] = kv;
}

// ---------------- one-pass register softmax over rows of length 2048 ---------
__device__ __forceinline__ float warpMax(float v){
    #pragma unroll
    for (int o = 16; o; o >>= 1) v = fmaxf(v, __shfl_xor_sync(0xffffffffu, v, o));
    return v;
}
__device__ __forceinline__ float warpSum(float v){
    #pragma unroll
    for (int o = 16; o; o >>= 1) v += __shfl_xor_sync(0xffffffffu, v, o);
    return v;
}

__global__ void __launch_bounds__(256) softmax_rows(float* __restrict__ sc)
{
    float* row = sc + (long)blockIdx.x * SEQ;
    const int t = threadIdx.x;
    float4 a = *(float4*)(row + 4*t);
    float4 b = *(float4*)(row + 1024 + 4*t);

    float m = fmaxf(fmaxf(fmaxf(a.x, a.y), fmaxf(a.z, a.w)),
                    fmaxf(fmaxf(b.x, b.y), fmaxf(b.z, b.w)));
    __shared__ float sm[8], ss[8];
    float wm = warpMax(m);
    if ((t & 31) == 0) sm[t >> 5] = wm;
    __syncthreads();
    if (t < 32) { float x = (t < 8) ? sm[t] : -INFINITY; x = warpMax(x); if (t == 0) sm[0] = x; }
    __syncthreads();
    const float bm = sm[0];

    a.x = __expf(a.x - bm); a.y = __expf(a.y - bm); a.z = __expf(a.z - bm); a.w = __expf(a.w - bm);
    b.x = __expf(b.x - bm); b.y = __expf(b.y - bm); b.z = __expf(b.z - bm); b.w = __expf(b.w - bm);
    float s = a.x + a.y + a.z + a.w + b.x + b.y + b.z + b.w;
    float wsu = warpSum(s);
    if ((t & 31) == 0) ss[t >> 5] = wsu;
    __syncthreads();
    if (t < 32) { float x = (t < 8) ? ss[t] : 0.f; x = warpSum(x); if (t == 0) ss[0] = x; }
    __syncthreads();
    const float inv = 1.f / ss[0];

    a.x *= inv; a.y *= inv; a.z *= inv; a.w *= inv;
    b.x *= inv; b.y *= inv; b.z *= inv; b.w *= inv;
    *(float4*)(row + 4*t) = a;
    *(float4*)(row + 1024 + 4*t) = b;
}

// ---------------- launch ------------------------------------------------------
extern "C" void kernel_launch(void* const* d_in, const int* in_sizes, int n_in,
                              void* d_out, int out_size)
{
    const float* h     = (const float*)d_in[0];
    const float* W_dkv = (const float*)d_in[1];
    const float* b_dkv = (const float*)d_in[2];
    const float* W_dq  = (const float*)d_in[3];
    const float* b_dq  = (const float*)d_in[4];
    const float* W_uk  = (const float*)d_in[5];
    const float* b_uk  = (const float*)d_in[6];
    const float* W_uv  = (const float*)d_in[7];
    const float* b_uv  = (const float*)d_in[8];
    const float* W_uq  = (const float*)d_in[9];
    const float* b_uq  = (const float*)d_in[10];
    const float* W_qr  = (const float*)d_in[11];
    const float* b_qr  = (const float*)d_in[12];
    const float* W_kr  = (const float*)d_in[13];
    const float* b_kr  = (const float*)d_in[14];
    const float* W_o   = (const float*)d_in[15];
    const float* b_o   = (const float*)d_in[16];
    float* out = (float*)d_out;

    float *ckv, *cq, *qb, *kb, *qr, *kr, *q, *k, *v, *vT, *sc, *ao;
    float *wdkvT, *wdqT, *wkrT, *wukT, *wuvT, *wuqT, *wqrT, *woT;
    cudaGetSymbolAddress((void**)&ckv, g_ckv);
    cudaGetSymbolAddress((void**)&cq,  g_cq);
    cudaGetSymbolAddress((void**)&qb,  g_qbase);
    cudaGetSymbolAddress((void**)&kb,  g_kbase);
    cudaGetSymbolAddress((void**)&qr,  g_qrot);
    cudaGetSymbolAddress((void**)&kr,  g_krot);
    cudaGetSymbolAddress((void**)&q,   g_q);
    cudaGetSymbolAddress((void**)&k,   g_k);
    cudaGetSymbolAddress((void**)&v,   g_v);
    cudaGetSymbolAddress((void**)&vT,  g_vT);
    cudaGetSymbolAddress((void**)&sc,  g_sc);
    cudaGetSymbolAddress((void**)&ao,  g_ao);
    cudaGetSymbolAddress((void**)&wdkvT, g_wdkvT);
    cudaGetSymbolAddress((void**)&wdqT,  g_wdqT);
    cudaGetSymbolAddress((void**)&wkrT,  g_wkrT);
    cudaGetSymbolAddress((void**)&wukT,  g_wukT);
    cudaGetSymbolAddress((void**)&wuvT,  g_wuvT);
    cudaGetSymbolAddress((void**)&wuqT,  g_wuqT);
    cudaGetSymbolAddress((void**)&wqrT,  g_wqrT);
    cudaGetSymbolAddress((void**)&woT,   g_woT);

    cudaFuncSetAttribute(gemm_mma, cudaFuncAttributeMaxDynamicSharedMemorySize, GEMM_SMEM);

    const dim3 T256(256);
    const long SS  = (long)SEQ * SEQ;
    const long ROW = (long)SEQ * NFULL;

    // ---- weight transposes ([K,N] -> [N,K]) ----
    transpose_w<<<dim3(DKV/32, DMODEL/32), T256>>>(W_dkv, DKV, wdkvT, DMODEL, DMODEL, DKV);
    transpose_w<<<dim3(DKV/32, DMODEL/32), T256>>>(W_dq,  DKV, wdqT,  DMODEL, DMODEL, DKV);
    transpose_w<<<dim3((NH*DROPE)/32, DMODEL/32), T256>>>(W_kr, NH*DROPE, wkrT, DMODEL, DMODEL, NH*DROPE);
    transpose_w<<<dim3(NBASE/32, DKV/32), T256>>>(W_uk, NBASE, wukT, DKV, DKV, NBASE);
    transpose_w<<<dim3(NFULL/32, DKV/32), T256>>>(W_uv, NFULL, wuvT, DKV, DKV, NFULL);
    transpose_w<<<dim3(NBASE/32, DKV/32), T256>>>(W_uq, NBASE, wuqT, DKV, DKV, NBASE);
    transpose_w<<<dim3((NH*DROPE)/32, DKV/32), T256>>>(W_qr, NH*DROPE, wqrT, DKV, DKV, NH*DROPE);
    transpose_w<<<dim3(DMODEL/32, DMODEL/32), T256>>>(W_o, DMODEL, woT, DMODEL, DMODEL, DMODEL);

    // ---- down-projections: C = h @ W^T ----
    gemm_mma<<<dim3(DKV/128, BS/128, 1), T256, GEMM_SMEM>>>(BS, DKV, DMODEL,
        h, DMODEL, 0, 0, wdkvT, DMODEL, 0, 0, ckv, DKV, 0, 0, b_dkv, 1.f, 1);
    gemm_mma<<<dim3(DKV/128, BS/128, 1), T256, GEMM_SMEM>>>(BS, DKV, DMODEL,
        h, DMODEL, 0, 0, wdqT, DMODEL, 0, 0, cq, DKV, 0, 0, b_dq, 1.f, 1);
    gemm_mma<<<dim3((NH*DROPE)/128, BS/128, 1), T256, GEMM_SMEM>>>(BS, NH*DROPE, DMODEL,
        h, DMODEL, 0, 0, wkrT, DMODEL, 0, 0, kr, NH*DROPE, 0, 0, b_kr, 1.f, 1);

    // ---- up-projections (K=128) ----
    gemm_mma<<<dim3(NBASE/128, BS/128, 1), T256, GEMM_SMEM>>>(BS, NBASE, DKV,
        ckv, DKV, 0, 0, wukT, DKV, 0, 0, kb, NBASE, 0, 0, b_uk, 1.f, 1);
    gemm_mma<<<dim3(NFULL/128, BS/128, 1), T256, GEMM_SMEM>>>(BS, NFULL, DKV,
        ckv, DKV, 0, 0, wuvT, DKV, 0, 0, v, NFULL, 0, 0, b_uv, 1.f, 1);
    gemm_mma<<<dim3(NBASE/128, BS/128, 1), T256, GEMM_SMEM>>>(BS, NBASE, DKV,
        cq, DKV, 0, 0, wuqT, DKV, 0, 0, qb, NBASE, 0, 0, b_uq, 1.f, 1);
    gemm_mma<<<dim3((NH*DROPE)/128, BS/128, 1), T256, GEMM_SMEM>>>(BS, NH*DROPE, DKV,
        cq, DKV, 0, 0, wqrT, DKV, 0, 0, qr, NH*DROPE, 0, 0, b_qr, 1.f, 1);

    // ---- pack q/k + RoPE; transpose v per head ----
    {
        long total = (long)BS * NH * DHEAD;
        pack_rope<<<(int)((total + 255) / 256), T256>>>(qb, qr, kb, kr, q, k);
    }
    transpose_v<<<dim3(DHEAD/32, SEQ/32, BATCH*NH), T256>>>(v, vT);

    // ---- scores = q @ k^T / sqrt(D_HEAD) ----
    const float scScale = 1.f / sqrtf((float)DHEAD);
    gemm_mma<<<dim3(SEQ/128, SEQ/128, BATCH*NH), T256, GEMM_SMEM>>>(SEQ, SEQ, DHEAD,
        q, NFULL, ROW, DHEAD,
        k, NFULL, ROW, DHEAD,
        sc, SEQ, (long)NH*SS, SS,
        (const float*)nullptr, scScale, NH);

    // ---- softmax ----
    softmax_rows<<<BATCH*NH*SEQ, T256>>>(sc);

    // ---- ao = attn @ v  (B operand = per-head transposed v) ----
    gemm_mma<<<dim3(DHEAD/128, SEQ/128, BATCH*NH), T256, GEMM_SMEM>>>(SEQ, DHEAD, SEQ,
        sc, SEQ, (long)NH*SS, SS,
        vT, SEQ, (long)NH*DHEAD*SEQ, (long)DHEAD*SEQ,
        ao, NFULL, ROW, DHEAD,
        (const float*)nullptr, 1.f, NH);

    // ---- final projection ----
    gemm_mma<<<dim3(DMODEL/128, BS/128, 1), T256, GEMM_SMEM>>>(BS, DMODEL, DMODEL,
        ao, DMODEL, 0, 0, woT, DMODEL, 0, 0, out, DMODEL, 0, 0, b_o, 1.f, 1);
}

// round 7
// speedup vs baseline: 3.8455x; 1.1817x over previous
#include <cuda_runtime.h>
#include <cstdint>
#include <math.h>

// ---------------- problem constants ----------------
#define BATCH  2
#define SEQ    2048
#define DMODEL 5120
#define NH     8
#define DHEAD  640
#define DROPE  16
#define SPLITD 624
#define DKV    128
#define BS     (BATCH*SEQ)            // 4096 rows
#define NBASE  (NH*SPLITD)            // 4992
#define NFULL  (NH*DHEAD)             // 5120

// ---------------- scratch (device globals; no allocations allowed) ----------
__device__ __align__(128) float g_h32  [(long)BS*DMODEL];
__device__ __align__(128) float g_ckv  [BS*DKV];
__device__ __align__(128) float g_cq   [BS*DKV];
__device__ __align__(128) float g_qbase[(long)BS*NBASE];
__device__ __align__(128) float g_kbase[(long)BS*NBASE];
__device__ __align__(128) float g_qrot [BS*NH*DROPE];
__device__ __align__(128) float g_krot [BS*NH*DROPE];
__device__ __align__(128) float g_q    [(long)BS*NFULL];
__device__ __align__(128) float g_k    [(long)BS*NFULL];
__device__ __align__(128) float g_v    [(long)BS*NFULL];
__device__ __align__(128) float g_vT   [(long)BS*NFULL];
__device__ __align__(128) float g_sc   [(long)BATCH*NH*SEQ*SEQ];
__device__ __align__(128) float g_ao   [(long)BS*NFULL];
// transposed weights ([N,K] K-major for NT GEMM), pre-rounded to tf32
__device__ __align__(128) float g_wdkvT[DKV*DMODEL];
__device__ __align__(128) float g_wdqT [DKV*DMODEL];
__device__ __align__(128) float g_wkrT [NH*DROPE*DMODEL];
__device__ __align__(128) float g_wukT [(long)NBASE*DKV];
__device__ __align__(128) float g_wuvT [(long)NFULL*DKV];
__device__ __align__(128) float g_wuqT [(long)NBASE*DKV];
__device__ __align__(128) float g_wqrT [NH*DROPE*DKV];
__device__ __align__(128) float g_woT  [(long)DMODEL*DMODEL];

// ---------------- tf32 helpers (portable PTX, no 'a' features) --------------
__device__ __forceinline__ uint32_t tf32r(float x) {
    uint32_t r;
    asm("cvt.rna.tf32.f32 %0, %1;" : "=r"(r) : "f"(x));
    return r;
}
__device__ __forceinline__ float rtf(float x) { return __uint_as_float(tf32r(x)); }

#define MMA_TF32(c, a, b) \
    asm volatile("mma.sync.aligned.m16n8k8.row.col.f32.tf32.tf32.f32 " \
        "{%0,%1,%2,%3}, {%4,%5,%6,%7}, {%8,%9}, {%0,%1,%2,%3};" \
        : "+f"((c)[0]), "+f"((c)[1]), "+f"((c)[2]), "+f"((c)[3]) \
        : "r"((a)[0]), "r"((a)[1]), "r"((a)[2]), "r"((a)[3]), \
          "r"((b)[0]), "r"((b)[1]))

__device__ __forceinline__ uint32_t smem_to_u32(const void* p) {
    uint32_t a;
    asm("{ .reg .u64 t; cvta.to.shared.u64 t, %1; cvt.u32.u64 %0, t; }" : "=r"(a) : "l"(p));
    return a;
}

#define CP16(dst, src) \
    asm volatile("cp.async.cg.shared.global [%0], [%1], 16;" :: "r"(dst), "l"(src))
#define CP_COMMIT() asm volatile("cp.async.commit_group;")
#define CP_WAIT1()  asm volatile("cp.async.wait_group 1;")
#define CP_WAIT0()  asm volatile("cp.async.wait_group 0;")

// =================== tf32 mma.sync NT GEMM, cp.async 3-stage =================
// C[m,n] = scale * sum_k A[m*lda+k] * B[n*ldb+k] (+ bias[n]); optional tf32
// rounding of the output (rnd). Inputs MUST already be tf32-rounded fp32.
// M%128==0, N%128==0, K%32==0, K>=96.
// CTA: 128x128 tile, 256 threads (8 warps, 4M x 2N), warp tile 32x64.
#define NSTG  3
#define SAK   36                      // smem row stride (floats): conflict-free frags
#define STG_F (128*SAK)               // floats per operand per stage (4608)
#define GEMM_SMEM (NSTG*2*STG_F*4)    // 110592 bytes

__global__ void __launch_bounds__(256, 2) gemm_mma(
    int M, int N, int K,
    const float* __restrict__ A, int lda, long offA_b, long offA_h,
    const float* __restrict__ B, int ldb, long offB_b, long offB_h,
    float* __restrict__ C, int ldc, long offC_b, long offC_h,
    const float* __restrict__ bias, float scale, int nh, int rnd)
{
    extern __shared__ float smf[];
    const int tid  = threadIdx.x;
    const int wid  = tid >> 5, lane = tid & 31;
    const int g    = lane >> 2, tq = lane & 3;
    const int warpM = wid >> 1, warpN = wid & 1;

    const int z  = blockIdx.z;
    const int bz = z / nh, hz = z - bz*nh;
    A += (long)bz*offA_b + (long)hz*offA_h;
    B += (long)bz*offB_b + (long)hz*offB_h;
    C += (long)bz*offC_b + (long)hz*offC_h;

    const int mBase = blockIdx.y * 128;
    const int nBase = blockIdx.x * 128;
    const float* Ag = A + (long)mBase*lda;
    const float* Bg = B + (long)nBase*ldb;
    const uint32_t sb = smem_to_u32(smf);

    // per-thread gmem->smem mapping: 4 float4 per operand per stage
    int arow[4], acol[4];
    #pragma unroll
    for (int i = 0; i < 4; i++) {
        int f = i*256 + tid;
        arow[i] = f >> 3;
        acol[i] = (f & 7) << 2;
    }

    float acc[2][8][4];
    #pragma unroll
    for (int mt = 0; mt < 2; mt++)
        #pragma unroll
        for (int nt = 0; nt < 8; nt++)
            #pragma unroll
            for (int r = 0; r < 4; r++) acc[mt][nt][r] = 0.f;

    const int T = K / 32;

#define ISSUE(t) do { \
    const float* _Ak = Ag + (t)*32; const float* _Bk = Bg + (t)*32; \
    const uint32_t _d = sb + (uint32_t)(((t) % NSTG) * (2*STG_F*4)); \
    _Pragma("unroll") \
    for (int i = 0; i < 4; i++) { \
        const uint32_t _o = (uint32_t)(arow[i]*SAK + acol[i]) * 4u; \
        CP16(_d + _o,             _Ak + (long)arow[i]*lda + acol[i]); \
        CP16(_d + STG_F*4u + _o,  _Bk + (long)arow[i]*ldb + acol[i]); \
    } \
    CP_COMMIT(); } while (0)

    ISSUE(0);
    ISSUE(1);

    for (int t = 0; t < T; ++t) {
        if (t == T-1) { CP_WAIT0(); } else { CP_WAIT1(); }
        __syncthreads();
        if (t + 2 < T) ISSUE(t+2);

        const float* As = smf + (t % NSTG)*(2*STG_F);
        const float* Bs = As + STG_F;
        #pragma unroll
        for (int ks = 0; ks < 4; ks++) {
            const int k0 = ks << 3;
            uint32_t afr[2][4], bfr[8][2];
            #pragma unroll
            for (int mt = 0; mt < 2; mt++) {
                const int m = warpM*32 + mt*16 + g;
                afr[mt][0] = __float_as_uint(As[(m    )*SAK + k0 + tq    ]);
                afr[mt][1] = __float_as_uint(As[(m + 8)*SAK + k0 + tq    ]);
                afr[mt][2] = __float_as_uint(As[(m    )*SAK + k0 + tq + 4]);
                afr[mt][3] = __float_as_uint(As[(m + 8)*SAK + k0 + tq + 4]);
            }
            #pragma unroll
            for (int nt = 0; nt < 8; nt++) {
                const int n = warpN*64 + nt*8 + g;
                bfr[nt][0] = __float_as_uint(Bs[n*SAK + k0 + tq    ]);
                bfr[nt][1] = __float_as_uint(Bs[n*SAK + k0 + tq + 4]);
            }
            #pragma unroll
            for (int mt = 0; mt < 2; mt++)
                #pragma unroll
                for (int nt = 0; nt < 8; nt++)
                    MMA_TF32(acc[mt][nt], afr[mt], bfr[nt]);
        }
    }
#undef ISSUE

    // epilogue
    #pragma unroll
    for (int mt = 0; mt < 2; mt++) {
        const int m0 = mBase + warpM*32 + mt*16 + g;
        #pragma unroll
        for (int nt = 0; nt < 8; nt++) {
            const int nc = nBase + warpN*64 + nt*8 + 2*tq;
            float2 lo, hi;
            lo.x = acc[mt][nt][0]*scale; lo.y = acc[mt][nt][1]*scale;
            hi.x = acc[mt][nt][2]*scale; hi.y = acc[mt][nt][3]*scale;
            if (bias) {
                float bx = bias[nc], by = bias[nc+1];
                lo.x += bx; lo.y += by; hi.x += bx; hi.y += by;
            }
            if (rnd) {
                lo.x = rtf(lo.x); lo.y = rtf(lo.y);
                hi.x = rtf(hi.x); hi.y = rtf(hi.y);
            }
            *(float2*)(C + (long)m0*ldc + nc)       = lo;
            *(float2*)(C + (long)(m0 + 8)*ldc + nc) = hi;
        }
    }
}

// ---------------- elementwise tf32 round-copy (for input h) -----------------
__global__ void __launch_bounds__(256) round_copy(
    const float* __restrict__ in, float* __restrict__ out, long n4)
{
    long i = (long)blockIdx.x * blockDim.x + threadIdx.x;
    if (i >= n4) return;
    float4 v = *(const float4*)(in + 4*i);
    v.x = rtf(v.x); v.y = rtf(v.y); v.z = rtf(v.z); v.w = rtf(v.w);
    *(float4*)(out + 4*i) = v;
}

// =================== transpose kernels (tf32-rounding) =======================
__global__ void __launch_bounds__(256) transpose_w(
    const float* __restrict__ in, int ldin,
    float* __restrict__ out, int ldout, int R, int Ccols)
{
    __shared__ float tile[32][33];
    const int tx = threadIdx.x & 31, ty = threadIdx.x >> 5;
    const int bx = blockIdx.x * 32, by = blockIdx.y * 32;
    #pragma unroll
    for (int j = ty; j < 32; j += 8) {
        int r = by + j, c = bx + tx;
        if (r < R && c < Ccols) tile[j][tx] = in[(long)r*ldin + c];
    }
    __syncthreads();
    #pragma unroll
    for (int j = ty; j < 32; j += 8) {
        int r = bx + j, c = by + tx;
        if (r < Ccols && c < R) out[(long)r*ldout + c] = rtf(tile[tx][j]);
    }
}

// v[b, s, h*640+d] -> vT[(b*NH+h), d, s], tf32-rounded
__global__ void __launch_bounds__(256) transpose_v(
    const float* __restrict__ v, float* __restrict__ vT)
{
    __shared__ float tile[32][33];
    const int z = blockIdx.z;
    const int b = z >> 3, h = z & 7;
    const float* in = v + (long)b*SEQ*NFULL + h*DHEAD;
    float* out = vT + (long)z*DHEAD*SEQ;
    const int tx = threadIdx.x & 31, ty = threadIdx.x >> 5;
    const int bx = blockIdx.x * 32;   // d
    const int by = blockIdx.y * 32;   // s
    #pragma unroll
    for (int j = ty; j < 32; j += 8) {
        tile[j][tx] = in[(long)(by + j)*NFULL + bx + tx];
    }
    __syncthreads();
    #pragma unroll
    for (int j = ty; j < 32; j += 8) {
        out[(long)(bx + j)*SEQ + by + tx] = rtf(tile[tx][j]);
    }
}

// ---------------- pack q/k (concat base + rotated rope), tf32-rounded --------
__global__ void __launch_bounds__(256) pack_rope(
    const float* __restrict__ qbase, const float* __restrict__ qrot,
    const float* __restrict__ kbase, const float* __restrict__ krot,
    float* __restrict__ q, float* __restrict__ k)
{
    long idx = (long)blockIdx.x * blockDim.x + threadIdx.x;
    const long total = (long)BS * NH * DHEAD;
    if (idx >= total) return;
    int d  = (int)(idx % DHEAD);
    int hh = (int)((idx / DHEAD) % NH);
    long bs = idx / ((long)DHEAD * NH);
    float qv, kv;
    if (d < SPLITD) {
        qv = qbase[bs*NBASE + hh*SPLITD + d];
        kv = kbase[bs*NBASE + hh*SPLITD + d];
    } else {
        int i = d - SPLITD;   // 0..15
        const float* qr = qrot + bs*(NH*DROPE) + hh*DROPE;
        const float* kr = krot + bs*(NH*DROPE) + hh*DROPE;
        if (i < 8) {
            int s = (int)(bs % SEQ);
            int j = i & 3;
            float invf = (j == 0) ? 1.f : (j == 1) ? 0.1f : (j == 2) ? 0.01f : 0.001f;
            float ang = ((float)s / 40.0f) * invf;
            float c = cosf(ang), sn = sinf(ang);
            if (i < 4) { qv = qr[i]*c - qr[i+4]*sn;  kv = kr[i]*c - kr[i+4]*sn; }
            else       { qv = qr[i]*c + qr[i-4]*sn;  kv = kr[i]*c + kr[i-4]*sn; }
        } else {
            qv = qr[i]; kv = kr[i];
        }
    }
    q[idx] = rtf(qv); k[idx] = rtf(kv);
}

// ---------------- one-pass register softmax over rows of length 2048 ---------
__device__ __forceinline__ float warpMax(float v){
    #pragma unroll
    for (int o = 16; o; o >>= 1) v = fmaxf(v, __shfl_xor_sync(0xffffffffu, v, o));
    return v;
}
__device__ __forceinline__ float warpSum(float v){
    #pragma unroll
    for (int o = 16; o; o >>= 1) v += __shfl_xor_sync(0xffffffffu, v, o);
    return v;
}

__global__ void __launch_bounds__(256) softmax_rows(float* __restrict__ sc)
{
    float* row = sc + (long)blockIdx.x * SEQ;
    const int t = threadIdx.x;
    float4 a = *(float4*)(row + 4*t);
    float4 b = *(float4*)(row + 1024 + 4*t);

    float m = fmaxf(fmaxf(fmaxf(a.x, a.y), fmaxf(a.z, a.w)),
                    fmaxf(fmaxf(b.x, b.y), fmaxf(b.z, b.w)));
    __shared__ float sm[8], ss[8];
    float wm = warpMax(m);
    if ((t & 31) == 0) sm[t >> 5] = wm;
    __syncthreads();
    if (t < 32) { float x = (t < 8) ? sm[t] : -INFINITY; x = warpMax(x); if (t == 0) sm[0] = x; }
    __syncthreads();
    const float bm = sm[0];

    a.x = __expf(a.x - bm); a.y = __expf(a.y - bm); a.z = __expf(a.z - bm); a.w = __expf(a.w - bm);
    b.x = __expf(b.x - bm); b.y = __expf(b.y - bm); b.z = __expf(b.z - bm); b.w = __expf(b.w - bm);
    float s = a.x + a.y + a.z + a.w + b.x + b.y + b.z + b.w;
    float wsu = warpSum(s);
    if ((t & 31) == 0) ss[t >> 5] = wsu;
    __syncthreads();
    if (t < 32) { float x = (t < 8) ? ss[t] : 0.f; x = warpSum(x); if (t == 0) ss[0] = x; }
    __syncthreads();
    const float inv = 1.f / ss[0];

    a.x = rtf(a.x*inv); a.y = rtf(a.y*inv); a.z = rtf(a.z*inv); a.w = rtf(a.w*inv);
    b.x = rtf(b.x*inv); b.y = rtf(b.y*inv); b.z = rtf(b.z*inv); b.w = rtf(b.w*inv);
    *(float4*)(row + 4*t) = a;
    *(float4*)(row + 1024 + 4*t) = b;
}

// ---------------- launch ------------------------------------------------------
extern "C" void kernel_launch(void* const* d_in, const int* in_sizes, int n_in,
                              void* d_out, int out_size)
{
    const float* h     = (const float*)d_in[0];
    const float* W_dkv = (const float*)d_in[1];
    const float* b_dkv = (const float*)d_in[2];
    const float* W_dq  = (const float*)d_in[3];
    const float* b_dq  = (const float*)d_in[4];
    const float* W_uk  = (const float*)d_in[5];
    const float* b_uk  = (const float*)d_in[6];
    const float* W_uv  = (const float*)d_in[7];
    const float* b_uv  = (const float*)d_in[8];
    const float* W_uq  = (const float*)d_in[9];
    const float* b_uq  = (const float*)d_in[10];
    const float* W_qr  = (const float*)d_in[11];
    const float* b_qr  = (const float*)d_in[12];
    const float* W_kr  = (const float*)d_in[13];
    const float* b_kr  = (const float*)d_in[14];
    const float* W_o   = (const float*)d_in[15];
    const float* b_o   = (const float*)d_in[16];
    float* out = (float*)d_out;

    float *h32, *ckv, *cq, *qb, *kb, *qr, *kr, *q, *k, *v, *vT, *sc, *ao;
    float *wdkvT, *wdqT, *wkrT, *wukT, *wuvT, *wuqT, *wqrT, *woT;
    cudaGetSymbolAddress((void**)&h32, g_h32);
    cudaGetSymbolAddress((void**)&ckv, g_ckv);
    cudaGetSymbolAddress((void**)&cq,  g_cq);
    cudaGetSymbolAddress((void**)&qb,  g_qbase);
    cudaGetSymbolAddress((void**)&kb,  g_kbase);
    cudaGetSymbolAddress((void**)&qr,  g_qrot);
    cudaGetSymbolAddress((void**)&kr,  g_krot);
    cudaGetSymbolAddress((void**)&q,   g_q);
    cudaGetSymbolAddress((void**)&k,   g_k);
    cudaGetSymbolAddress((void**)&v,   g_v);
    cudaGetSymbolAddress((void**)&vT,  g_vT);
    cudaGetSymbolAddress((void**)&sc,  g_sc);
    cudaGetSymbolAddress((void**)&ao,  g_ao);
    cudaGetSymbolAddress((void**)&wdkvT, g_wdkvT);
    cudaGetSymbolAddress((void**)&wdqT,  g_wdqT);
    cudaGetSymbolAddress((void**)&wkrT,  g_wkrT);
    cudaGetSymbolAddress((void**)&wukT,  g_wukT);
    cudaGetSymbolAddress((void**)&wuvT,  g_wuvT);
    cudaGetSymbolAddress((void**)&wuqT,  g_wuqT);
    cudaGetSymbolAddress((void**)&wqrT,  g_wqrT);
    cudaGetSymbolAddress((void**)&woT,   g_woT);

    cudaFuncSetAttribute(gemm_mma, cudaFuncAttributeMaxDynamicSharedMemorySize, GEMM_SMEM);

    const dim3 T256(256);
    const long SS  = (long)SEQ * SEQ;
    const long ROW = (long)SEQ * NFULL;

    // ---- tf32-round the input h ----
    {
        long n4 = ((long)BS * DMODEL) / 4;
        round_copy<<<(int)((n4 + 255) / 256), T256>>>(h, h32, n4);
    }

    // ---- weight transposes ([K,N] -> [N,K]) + tf32 round ----
    transpose_w<<<dim3(DKV/32, DMODEL/32), T256>>>(W_dkv, DKV, wdkvT, DMODEL, DMODEL, DKV);
    transpose_w<<<dim3(DKV/32, DMODEL/32), T256>>>(W_dq,  DKV, wdqT,  DMODEL, DMODEL, DKV);
    transpose_w<<<dim3((NH*DROPE)/32, DMODEL/32), T256>>>(W_kr, NH*DROPE, wkrT, DMODEL, DMODEL, NH*DROPE);
    transpose_w<<<dim3(NBASE/32, DKV/32), T256>>>(W_uk, NBASE, wukT, DKV, DKV, NBASE);
    transpose_w<<<dim3(NFULL/32, DKV/32), T256>>>(W_uv, NFULL, wuvT, DKV, DKV, NFULL);
    transpose_w<<<dim3(NBASE/32, DKV/32), T256>>>(W_uq, NBASE, wuqT, DKV, DKV, NBASE);
    transpose_w<<<dim3((NH*DROPE)/32, DKV/32), T256>>>(W_qr, NH*DROPE, wqrT, DKV, DKV, NH*DROPE);
    transpose_w<<<dim3(DMODEL/32, DMODEL/32), T256>>>(W_o, DMODEL, woT, DMODEL, DMODEL, DMODEL);

    // ---- down-projections: C = h @ W^T (outputs feeding GEMMs get rnd=1) ----
    gemm_mma<<<dim3(DKV/128, BS/128, 1), T256, GEMM_SMEM>>>(BS, DKV, DMODEL,
        h32, DMODEL, 0, 0, wdkvT, DMODEL, 0, 0, ckv, DKV, 0, 0, b_dkv, 1.f, 1, 1);
    gemm_mma<<<dim3(DKV/128, BS/128, 1), T256, GEMM_SMEM>>>(BS, DKV, DMODEL,
        h32, DMODEL, 0, 0, wdqT, DMODEL, 0, 0, cq, DKV, 0, 0, b_dq, 1.f, 1, 1);
    gemm_mma<<<dim3((NH*DROPE)/128, BS/128, 1), T256, GEMM_SMEM>>>(BS, NH*DROPE, DMODEL,
        h32, DMODEL, 0, 0, wkrT, DMODEL, 0, 0, kr, NH*DROPE, 0, 0, b_kr, 1.f, 1, 0);

    // ---- up-projections (K=128) ----
    gemm_mma<<<dim3(NBASE/128, BS/128, 1), T256, GEMM_SMEM>>>(BS, NBASE, DKV,
        ckv, DKV, 0, 0, wukT, DKV, 0, 0, kb, NBASE, 0, 0, b_uk, 1.f, 1, 0);
    gemm_mma<<<dim3(NFULL/128, BS/128, 1), T256, GEMM_SMEM>>>(BS, NFULL, DKV,
        ckv, DKV, 0, 0, wuvT, DKV, 0, 0, v, NFULL, 0, 0, b_uv, 1.f, 1, 0);
    gemm_mma<<<dim3(NBASE/128, BS/128, 1), T256, GEMM_SMEM>>>(BS, NBASE, DKV,
        cq, DKV, 0, 0, wuqT, DKV, 0, 0, qb, NBASE, 0, 0, b_uq, 1.f, 1, 0);
    gemm_mma<<<dim3((NH*DROPE)/128, BS/128, 1), T256, GEMM_SMEM>>>(BS, NH*DROPE, DKV,
        cq, DKV, 0, 0, wqrT, DKV, 0, 0, qr, NH*DROPE, 0, 0, b_qr, 1.f, 1, 0);

    // ---- pack q/k + RoPE (rounds q,k); transpose v per head (rounds vT) ----
    {
        long total = (long)BS * NH * DHEAD;
        pack_rope<<<(int)((total + 255) / 256), T256>>>(qb, qr, kb, kr, q, k);
    }
    transpose_v<<<dim3(DHEAD/32, SEQ/32, BATCH*NH), T256>>>(v, vT);

    // ---- scores = q @ k^T / sqrt(D_HEAD) ----
    const float scScale = 1.f / sqrtf((float)DHEAD);
    gemm_mma<<<dim3(SEQ/128, SEQ/128, BATCH*NH), T256, GEMM_SMEM>>>(SEQ, SEQ, DHEAD,
        q, NFULL, ROW, DHEAD,
        k, NFULL, ROW, DHEAD,
        sc, SEQ, (long)NH*SS, SS,
        (const float*)nullptr, scScale, NH, 0);

    // ---- softmax (rounds probs) ----
    softmax_rows<<<BATCH*NH*SEQ, T256>>>(sc);

    // ---- ao = attn @ v  (B operand = per-head transposed v) ----
    gemm_mma<<<dim3(DHEAD/128, SEQ/128, BATCH*NH), T256, GEMM_SMEM>>>(SEQ, DHEAD, SEQ,
        sc, SEQ, (long)NH*SS, SS,
        vT, SEQ, (long)NH*DHEAD*SEQ, (long)DHEAD*SEQ,
        ao, NFULL, ROW, DHEAD,
        (const float*)nullptr, 1.f, NH, 1);

    // ---- final projection ----
    gemm_mma<<<dim3(DMODEL/128, BS/128, 1), T256, GEMM_SMEM>>>(BS, DMODEL, DMODEL,
        ao, DMODEL, 0, 0, woT, DMODEL, 0, 0, out, DMODEL, 0, 0, b_o, 1.f, 1, 0);
}

// round 12
// speedup vs baseline: 5.1814x; 1.3474x over previous
#include <cuda_runtime.h>
#include <cuda_fp16.h>
#include <cstdint>
#include <math.h>

// ---------------- problem constants ----------------
#define BATCH  2
#define SEQ    2048
#define DMODEL 5120
#define NH     8
#define DHEAD  640
#define DROPE  16
#define SPLITD 624
#define DKV    128
#define BS     (BATCH*SEQ)            // 4096 rows
#define NBASE  (NH*SPLITD)            // 4992
#define NFULL  (NH*DHEAD)             // 5120

// ---------------- scratch (device globals; no allocations allowed) ----------
__device__ __align__(128) __half g_h16 [(long)BS*DMODEL];
__device__ __align__(128) __half g_ckv [BS*DKV];
__device__ __align__(128) __half g_cq  [BS*DKV];
__device__ __align__(128) __half g_qb  [(long)BS*NBASE];
__device__ __align__(128) __half g_kb  [(long)BS*NBASE];
__device__ __align__(128) __half g_qr  [BS*NH*DROPE];
__device__ __align__(128) __half g_kr  [BS*NH*DROPE];
__device__ __align__(128) __half g_q   [(long)BS*NFULL];
__device__ __align__(128) __half g_k   [(long)BS*NFULL];
__device__ __align__(128) __half g_v   [(long)BS*NFULL];
__device__ __align__(128) __half g_vT  [(long)BS*NFULL];
__device__ __align__(128) float  g_sc  [(long)BATCH*NH*SEQ*SEQ];  // scores fp32
__device__ __align__(128) __half g_p16 [(long)BATCH*NH*SEQ*SEQ];  // probs fp16
__device__ __align__(128) __half g_ao  [(long)BS*NFULL];
// transposed weights ([N,K] K-major), fp16
__device__ __align__(128) __half g_wdkvT[DKV*DMODEL];
__device__ __align__(128) __half g_wdqT [DKV*DMODEL];
__device__ __align__(128) __half g_wkrT [NH*DROPE*DMODEL];
__device__ __align__(128) __half g_wukT [(long)NBASE*DKV];
__device__ __align__(128) __half g_wuvT [(long)NFULL*DKV];
__device__ __align__(128) __half g_wuqT [(long)NBASE*DKV];
__device__ __align__(128) __half g_wqrT [NH*DROPE*DKV];
__device__ __align__(128) __half g_woT  [(long)DMODEL*DMODEL];

// ---------------- helpers ----------------
__device__ __forceinline__ uint32_t smem_to_u32(const void* p) {
    uint32_t a;
    asm("{ .reg .u64 t; cvta.to.shared.u64 t, %1; cvt.u32.u64 %0, t; }" : "=r"(a) : "l"(p));
    return a;
}
__device__ __forceinline__ void cp16(uint32_t dst, const void* src) {
    asm volatile("cp.async.cg.shared.global [%0], [%1], 16;" :: "r"(dst), "l"(src));
}
__device__ __forceinline__ void cp_commit() { asm volatile("cp.async.commit_group;"); }
__device__ __forceinline__ void cp_wait1()  { asm volatile("cp.async.wait_group 1;"); }
__device__ __forceinline__ void cp_wait0()  { asm volatile("cp.async.wait_group 0;"); }

#define MMA_F16(c, a, b) \
    asm volatile("mma.sync.aligned.m16n8k16.row.col.f32.f16.f16.f32 " \
        "{%0,%1,%2,%3}, {%4,%5,%6,%7}, {%8,%9}, {%0,%1,%2,%3};" \
        : "+f"((c)[0]), "+f"((c)[1]), "+f"((c)[2]), "+f"((c)[3]) \
        : "r"((a)[0]), "r"((a)[1]), "r"((a)[2]), "r"((a)[3]), \
          "r"((b)[0]), "r"((b)[1]))

// =================== fp16 mma.sync NT GEMM, cp.async 3-stage =================
// C[m,n] = scale * sum_k A[m*lda+k]*B[n*ldb+k] (+ bias[n]).
// A, B fp16; C fp16 (outFloat=0) or fp32 (outFloat=1).
// M%128==0, N%128==0, K%64==0, K>=128.
// CTA 128x128, 256 threads (8 warps, 4M x 2N), warp tile 32x64, KC=64.
// Smem per stage per operand: 128 rows x 64 halves = 16KB, XOR-swizzled:
//   phys_chunk = chunk ^ (row & 7); rows are 128B apart.
#define STG_B 32768                    // bytes per stage (A 16K + B 16K)
#define GEMM_SMEM (3*STG_B)            // 98304

struct CpMap { int row[4]; int ck[4]; };

__device__ __forceinline__ void issue_stage(
    const CpMap& mp, uint32_t sb, int t,
    const __half* Ag, int lda, const __half* Bg, int ldb)
{
    const __half* Ak = Ag + (long)t*64;
    const __half* Bk = Bg + (long)t*64;
    const uint32_t d = sb + (uint32_t)((t % 3) * STG_B);
    #pragma unroll
    for (int i = 0; i < 4; i++) {
        const uint32_t o = (uint32_t)(mp.row[i]*128)
                         + (uint32_t)(((mp.ck[i] ^ (mp.row[i] & 7)) << 4));
        cp16(d + o,           Ak + (long)mp.row[i]*lda + mp.ck[i]*8);
        cp16(d + 16384u + o,  Bk + (long)mp.row[i]*ldb + mp.ck[i]*8);
    }
    cp_commit();
}

__global__ void __launch_bounds__(256, 2) gemm_h(
    int M, int N, int K,
    const __half* __restrict__ A, int lda, long offA_b, long offA_h,
    const __half* __restrict__ B, int ldb, long offB_b, long offB_h,
    void* __restrict__ Cv, int ldc, long offC_b, long offC_h,
    const float* __restrict__ bias, float scale, int nh, int outFloat)
{
    extern __shared__ char smc[];
    const int tid  = threadIdx.x;
    const int wid  = tid >> 5, lane = tid & 31;
    const int g    = lane >> 2, tq = lane & 3;
    const int warpM = wid >> 1, warpN = wid & 1;

    const int z  = blockIdx.z;
    const int bz = z / nh, hz = z - bz*nh;
    A += (long)bz*offA_b + (long)hz*offA_h;
    B += (long)bz*offB_b + (long)hz*offB_h;

    const int mBase = blockIdx.y * 128;
    const int nBase = blockIdx.x * 128;
    const __half* Ag = A + (long)mBase*lda;
    const __half* Bg = B + (long)nBase*ldb;
    const uint32_t sb = smem_to_u32(smc);

    CpMap mp;
    #pragma unroll
    for (int i = 0; i < 4; i++) {
        int f = i*256 + tid;
        mp.row[i] = f >> 3;
        mp.ck[i]  = f & 7;
    }

    float acc[2][8][4];
    #pragma unroll
    for (int mt = 0; mt < 2; mt++)
        #pragma unroll
        for (int nt = 0; nt < 8; nt++)
            #pragma unroll
            for (int r = 0; r < 4; r++) acc[mt][nt][r] = 0.f;

    const int T = K / 64;

    issue_stage(mp, sb, 0, Ag, lda, Bg, ldb);
    issue_stage(mp, sb, 1, Ag, lda, Bg, ldb);

    for (int t = 0; t < T; ++t) {
        if (t == T-1) cp_wait0(); else cp_wait1();
        __syncthreads();
        if (t + 2 < T) issue_stage(mp, sb, t+2, Ag, lda, Bg, ldb);

        const char* As = smc + (t % 3)*STG_B;
        const char* Bs = As + 16384;
        #pragma unroll
        for (int ks = 0; ks < 4; ks++) {
            const int x0 = (((ks*2    ) ^ g) << 4) + 4*tq;
            const int x1 = (((ks*2 + 1) ^ g) << 4) + 4*tq;
            uint32_t afr[2][4], bfr[8][2];
            #pragma unroll
            for (int mt = 0; mt < 2; mt++) {
                const char* ab = As + (warpM*32 + mt*16 + g)*128;
                afr[mt][0] = *(const uint32_t*)(ab + x0);
                afr[mt][1] = *(const uint32_t*)(ab + 1024 + x0);
                afr[mt][2] = *(const uint32_t*)(ab + x1);
                afr[mt][3] = *(const uint32_t*)(ab + 1024 + x1);
            }
            #pragma unroll
            for (int nt = 0; nt < 8; nt++) {
                const char* bb = Bs + (warpN*64 + nt*8 + g)*128;
                bfr[nt][0] = *(const uint32_t*)(bb + x0);
                bfr[nt][1] = *(const uint32_t*)(bb + x1);
            }
            #pragma unroll
            for (int mt = 0; mt < 2; mt++)
                #pragma unroll
                for (int nt = 0; nt < 8; nt++)
                    MMA_F16(acc[mt][nt], afr[mt], bfr[nt]);
        }
    }

    // epilogue
    #pragma unroll
    for (int mt = 0; mt < 2; mt++) {
        const int m0 = mBase + warpM*32 + mt*16 + g;
        #pragma unroll
        for (int nt = 0; nt < 8; nt++) {
            const int nc = nBase + warpN*64 + nt*8 + 2*tq;
            float ax = acc[mt][nt][0]*scale, ay = acc[mt][nt][1]*scale;
            float bx = acc[mt][nt][2]*scale, by = acc[mt][nt][3]*scale;
            if (bias) {
                float u = bias[nc], w = bias[nc+1];
                ax += u; ay += w; bx += u; by += w;
            }
            if (outFloat) {
                float* C = (float*)Cv + (long)bz*offC_b + (long)hz*offC_h;
                *(float2*)(C + (long)m0*ldc + nc)     = make_float2(ax, ay);
                *(float2*)(C + (long)(m0+8)*ldc + nc) = make_float2(bx, by);
            } else {
                __half* C = (__half*)Cv + (long)bz*offC_b + (long)hz*offC_h;
                *(__half2*)(C + (long)m0*ldc + nc)     = __floats2half2_rn(ax, ay);
                *(__half2*)(C + (long)(m0+8)*ldc + nc) = __floats2half2_rn(bx, by);
            }
        }
    }
}

// ---------------- h (fp32) -> fp16 ----------------
__global__ void __launch_bounds__(256) round_h(
    const float* __restrict__ in, __half* __restrict__ out, long n4)
{
    long i = (long)blockIdx.x * blockDim.x + threadIdx.x;
    if (i >= n4) return;
    float4 v = ((const float4*)in)[i];
    ((__half2*)out)[2*i]   = __floats2half2_rn(v.x, v.y);
    ((__half2*)out)[2*i+1] = __floats2half2_rn(v.z, v.w);
}

// =================== transposes ===================
// weights: float in [R,C] -> half out [C,R]
__global__ void __launch_bounds__(256) transpose_w(
    const float* __restrict__ in, int ldin,
    __half* __restrict__ out, int ldout, int R, int Ccols)
{
    __shared__ float tile[32][33];
    const int tx = threadIdx.x & 31, ty = threadIdx.x >> 5;
    const int bx = blockIdx.x * 32, by = blockIdx.y * 32;
    #pragma unroll
    for (int j = ty; j < 32; j += 8) {
        int r = by + j, c = bx + tx;
        if (r < R && c < Ccols) tile[j][tx] = in[(long)r*ldin + c];
    }
    __syncthreads();
    #pragma unroll
    for (int j = ty; j < 32; j += 8) {
        int r = bx + j, c = by + tx;
        if (r < Ccols && c < R) out[(long)r*ldout + c] = __float2half_rn(tile[tx][j]);
    }
}

// v16[b,s,h*640+d] -> vT16[(b*NH+h), d, s]
__global__ void __launch_bounds__(256) transpose_v(
    const __half* __restrict__ v, __half* __restrict__ vT)
{
    __shared__ __half tile[32][34];
    const int z = blockIdx.z;
    const int b = z >> 3, h = z & 7;
    const __half* in = v + (long)b*SEQ*NFULL + h*DHEAD;
    __half* out = vT + (long)z*DHEAD*SEQ;
    const int tx = threadIdx.x & 31, ty = threadIdx.x >> 5;
    const int bx = blockIdx.x * 32;   // d
    const int by = blockIdx.y * 32;   // s
    #pragma unroll
    for (int j = ty; j < 32; j += 8)
        tile[j][tx] = in[(long)(by + j)*NFULL + bx + tx];
    __syncthreads();
    #pragma unroll
    for (int j = ty; j < 32; j += 8)
        out[(long)(bx + j)*SEQ + by + tx] = tile[tx][j];
}

// ---------------- pack q/k (concat base + rotated rope), fp16 ----------------
__global__ void __launch_bounds__(256) pack_rope(
    const __half* __restrict__ qbase, const __half* __restrict__ qrot,
    const __half* __restrict__ kbase, const __half* __restrict__ krot,
    __half* __restrict__ q, __half* __restrict__ k)
{
    long idx = (long)blockIdx.x * blockDim.x + threadIdx.x;
    const long total = (long)BS * NH * DHEAD;
    if (idx >= total) return;
    int d  = (int)(idx % DHEAD);
    int hh = (int)((idx / DHEAD) % NH);
    long bs = idx / ((long)DHEAD * NH);
    float qv, kv;
    if (d < SPLITD) {
        qv = __half2float(qbase[bs*NBASE + hh*SPLITD + d]);
        kv = __half2float(kbase[bs*NBASE + hh*SPLITD + d]);
    } else {
        int i = d - SPLITD;   // 0..15
        const __half* qr = qrot + bs*(NH*DROPE) + hh*DROPE;
        const __half* kr = krot + bs*(NH*DROPE) + hh*DROPE;
        if (i < 8) {
            int s = (int)(bs % SEQ);
            int j = i & 3;
            float invf = (j == 0) ? 1.f : (j == 1) ? 0.1f : (j == 2) ? 0.01f : 0.001f;
            float ang = ((float)s / 40.0f) * invf;
            float c = cosf(ang), sn = sinf(ang);
            if (i < 4) {
                qv = __half2float(qr[i])*c - __half2float(qr[i+4])*sn;
                kv = __half2float(kr[i])*c - __half2float(kr[i+4])*sn;
            } else {
                qv = __half2float(qr[i])*c + __half2float(qr[i-4])*sn;
                kv = __half2float(kr[i])*c + __half2float(kr[i-4])*sn;
            }
        } else {
            qv = __half2float(qr[i]); kv = __half2float(kr[i]);
        }
    }
    q[idx] = __float2half_rn(qv); k[idx] = __float2half_rn(kv);
}

// ---------------- softmax: fp32 scores in, fp16 probs out --------------------
__device__ __forceinline__ float warpMax(float v){
    #pragma unroll
    for (int o = 16; o; o >>= 1) v = fmaxf(v, __shfl_xor_sync(0xffffffffu, v, o));
    return v;
}
__device__ __forceinline__ float warpSum(float v){
    #pragma unroll
    for (int o = 16; o; o >>= 1) v += __shfl_xor_sync(0xffffffffu, v, o);
    return v;
}

__global__ void __launch_bounds__(256) softmax_rows(
    const float* __restrict__ sc, __half* __restrict__ p)
{
    const float* row = sc + (long)blockIdx.x * SEQ;
    __half* prow = p + (long)blockIdx.x * SEQ;
    const int t = threadIdx.x;
    float4 a = *(const float4*)(row + 4*t);
    float4 b = *(const float4*)(row + 1024 + 4*t);

    float m = fmaxf(fmaxf(fmaxf(a.x, a.y), fmaxf(a.z, a.w)),
                    fmaxf(fmaxf(b.x, b.y), fmaxf(b.z, b.w)));
    __shared__ float sm[8], ss[8];
    float wm = warpMax(m);
    if ((t & 31) == 0) sm[t >> 5] = wm;
    __syncthreads();
    if (t < 32) { float x = (t < 8) ? sm[t] : -INFINITY; x = warpMax(x); if (t == 0) sm[0] = x; }
    __syncthreads();
    const float bm = sm[0];

    a.x = __expf(a.x - bm); a.y = __expf(a.y - bm); a.z = __expf(a.z - bm); a.w = __expf(a.w - bm);
    b.x = __expf(b.x - bm); b.y = __expf(b.y - bm); b.z = __expf(b.z - bm); b.w = __expf(b.w - bm);
    float s = a.x + a.y + a.z + a.w + b.x + b.y + b.z + b.w;
    float wsu = warpSum(s);
    if ((t & 31) == 0) ss[t >> 5] = wsu;
    __syncthreads();
    if (t < 32) { float x = (t < 8) ? ss[t] : 0.f; x = warpSum(x); if (t == 0) ss[0] = x; }
    __syncthreads();
    const float inv = 1.f / ss[0];

    *(__half2*)(prow + 4*t)          = __floats2half2_rn(a.x*inv, a.y*inv);
    *(__half2*)(prow + 4*t + 2)      = __floats2half2_rn(a.z*inv, a.w*inv);
    *(__half2*)(prow + 1024 + 4*t)   = __floats2half2_rn(b.x*inv, b.y*inv);
    *(__half2*)(prow + 1024 + 4*t+2) = __floats2half2_rn(b.z*inv, b.w*inv);
}

// ---------------- launch ------------------------------------------------------
extern "C" void kernel_launch(void* const* d_in, const int* in_sizes, int n_in,
                              void* d_out, int out_size)
{
    const float* h     = (const float*)d_in[0];
    const float* W_dkv = (const float*)d_in[1];
    const float* b_dkv = (const float*)d_in[2];
    const float* W_dq  = (const float*)d_in[3];
    const float* b_dq  = (const float*)d_in[4];
    const float* W_uk  = (const float*)d_in[5];
    const float* b_uk  = (const float*)d_in[6];
    const float* W_uv  = (const float*)d_in[7];
    const float* b_uv  = (const float*)d_in[8];
    const float* W_uq  = (const float*)d_in[9];
    const float* b_uq  = (const float*)d_in[10];
    const float* W_qr  = (const float*)d_in[11];
    const float* b_qr  = (const float*)d_in[12];
    const float* W_kr  = (const float*)d_in[13];
    const float* b_kr  = (const float*)d_in[14];
    const float* W_o   = (const float*)d_in[15];
    const float* b_o   = (const float*)d_in[16];
    float* out = (float*)d_out;

    __half *h16, *ckv, *cq, *qb, *kb, *qr, *kr, *q, *k, *v, *vT, *p16, *ao;
    __half *wdkvT, *wdqT, *wkrT, *wukT, *wuvT, *wuqT, *wqrT, *woT;
    float *sc;
    cudaGetSymbolAddress((void**)&h16, g_h16);
    cudaGetSymbolAddress((void**)&ckv, g_ckv);
    cudaGetSymbolAddress((void**)&cq,  g_cq);
    cudaGetSymbolAddress((void**)&qb,  g_qb);
    cudaGetSymbolAddress((void**)&kb,  g_kb);
    cudaGetSymbolAddress((void**)&qr,  g_qr);
    cudaGetSymbolAddress((void**)&kr,  g_kr);
    cudaGetSymbolAddress((void**)&q,   g_q);
    cudaGetSymbolAddress((void**)&k,   g_k);
    cudaGetSymbolAddress((void**)&v,   g_v);
    cudaGetSymbolAddress((void**)&vT,  g_vT);
    cudaGetSymbolAddress((void**)&sc,  g_sc);
    cudaGetSymbolAddress((void**)&p16, g_p16);
    cudaGetSymbolAddress((void**)&ao,  g_ao);
    cudaGetSymbolAddress((void**)&wdkvT, g_wdkvT);
    cudaGetSymbolAddress((void**)&wdqT,  g_wdqT);
    cudaGetSymbolAddress((void**)&wkrT,  g_wkrT);
    cudaGetSymbolAddress((void**)&wukT,  g_wukT);
    cudaGetSymbolAddress((void**)&wuvT,  g_wuvT);
    cudaGetSymbolAddress((void**)&wuqT,  g_wuqT);
    cudaGetSymbolAddress((void**)&wqrT,  g_wqrT);
    cudaGetSymbolAddress((void**)&woT,   g_woT);

    cudaFuncSetAttribute(gemm_h, cudaFuncAttributeMaxDynamicSharedMemorySize, GEMM_SMEM);

    const dim3 T256(256);
    const long SS  = (long)SEQ * SEQ;
    const long ROW = (long)SEQ * NFULL;

    // #1: h -> fp16
    {
        long n4 = ((long)BS * DMODEL) / 4;
        round_h<<<(int)((n4 + 255) / 256), T256>>>(h, h16, n4);
    }
    // #2, #3: transposes needed by the first two GEMMs
    transpose_w<<<dim3(DKV/32, DMODEL/32), T256>>>(W_dkv, DKV, wdkvT, DMODEL, DMODEL, DKV);
    transpose_w<<<dim3(NBASE/32, DKV/32), T256>>>(W_uk, NBASE, wukT, DKV, DKV, NBASE);
    // #4: c_kv = h @ W_dkv^T
    gemm_h<<<dim3(DKV/128, BS/128, 1), T256, GEMM_SMEM>>>(BS, DKV, DMODEL,
        h16, DMODEL, 0, 0, wdkvT, DMODEL, 0, 0, ckv, DKV, 0, 0, b_dkv, 1.f, 1, 0);
    // #5: transpose W_dq
    transpose_w<<<dim3(DKV/32, DMODEL/32), T256>>>(W_dq, DKV, wdqT, DMODEL, DMODEL, DKV);
    // #6 (ncu -s 5 -c 1 lands here): k_base = c_kv @ W_uk^T
    gemm_h<<<dim3(NBASE/128, BS/128, 1), T256, GEMM_SMEM>>>(BS, NBASE, DKV,
        ckv, DKV, 0, 0, wukT, DKV, 0, 0, kb, NBASE, 0, 0, b_uk, 1.f, 1, 0);
    // remaining transposes + projections
    transpose_w<<<dim3(NFULL/32, DKV/32), T256>>>(W_uv, NFULL, wuvT, DKV, DKV, NFULL);
    gemm_h<<<dim3(DKV/128, BS/128, 1), T256, GEMM_SMEM>>>(BS, DKV, DMODEL,
        h16, DMODEL, 0, 0, wdqT, DMODEL, 0, 0, cq, DKV, 0, 0, b_dq, 1.f, 1, 0);
    gemm_h<<<dim3(NFULL/128, BS/128, 1), T256, GEMM_SMEM>>>(BS, NFULL, DKV,
        ckv, DKV, 0, 0, wuvT, DKV, 0, 0, v, NFULL, 0, 0, b_uv, 1.f, 1, 0);
    transpose_w<<<dim3(NBASE/32, DKV/32), T256>>>(W_uq, NBASE, wuqT, DKV, DKV, NBASE);
    gemm_h<<<dim3(NBASE/128, BS/128, 1), T256, GEMM_SMEM>>>(BS, NBASE, DKV,
        cq, DKV, 0, 0, wuqT, DKV, 0, 0, qb, NBASE, 0, 0, b_uq, 1.f, 1, 0);
    transpose_w<<<dim3((NH*DROPE)/32, DKV/32), T256>>>(W_qr, NH*DROPE, wqrT, DKV, DKV, NH*DROPE);
    gemm_h<<<dim3((NH*DROPE)/128, BS/128, 1), T256, GEMM_SMEM>>>(BS, NH*DROPE, DKV,
        cq, DKV, 0, 0, wqrT, DKV, 0, 0, qr, NH*DROPE, 0, 0, b_qr, 1.f, 1, 0);
    transpose_w<<<dim3((NH*DROPE)/32, DMODEL/32), T256>>>(W_kr, NH*DROPE, wkrT, DMODEL, DMODEL, NH*DROPE);
    gemm_h<<<dim3((NH*DROPE)/128, BS/128, 1), T256, GEMM_SMEM>>>(BS, NH*DROPE, DMODEL,
        h16, DMODEL, 0, 0, wkrT, DMODEL, 0, 0, kr, NH*DROPE, 0, 0, b_kr, 1.f, 1, 0);

    // pack q/k + RoPE; transpose v per head
    {
        long total = (long)BS * NH * DHEAD;
        pack_rope<<<(int)((total + 255) / 256), T256>>>(qb, qr, kb, kr, q, k);
    }
    transpose_v<<<dim3(DHEAD/32, SEQ/32, BATCH*NH), T256>>>(v, vT);

    // scores = q @ k^T / sqrt(D_HEAD) -> fp32
    const float scScale = 1.f / sqrtf((float)DHEAD);
    gemm_h<<<dim3(SEQ/128, SEQ/128, BATCH*NH), T256, GEMM_SMEM>>>(SEQ, SEQ, DHEAD,
        q, NFULL, ROW, DHEAD,
        k, NFULL, ROW, DHEAD,
        sc, SEQ, (long)NH*SS, SS,
        (const float*)nullptr, scScale, NH, 1);

    // softmax -> fp16 probs
    softmax_rows<<<BATCH*NH*SEQ, T256>>>(sc, p16);

    // ao = attn @ v
    gemm_h<<<dim3(DHEAD/128, SEQ/128, BATCH*NH), T256, GEMM_SMEM>>>(SEQ, DHEAD, SEQ,
        p16, SEQ, (long)NH*SS, SS,
        vT, SEQ, (long)NH*DHEAD*SEQ, (long)DHEAD*SEQ,
        ao, NFULL, ROW, DHEAD,
        (const float*)nullptr, 1.f, NH, 0);

    // final projection -> fp32 out
    transpose_w<<<dim3(DMODEL/32, DMODEL/32), T256>>>(W_o, DMODEL, woT, DMODEL, DMODEL, DMODEL);
    gemm_h<<<dim3(DMODEL/128, BS/128, 1), T256, GEMM_SMEM>>>(BS, DMODEL, DMODEL,
        ao, DMODEL, 0, 0, woT, DMODEL, 0, 0, out, DMODEL, 0, 0, b_o, 1.f, 1, 1);
}

// round 13
// speedup vs baseline: 9.5637x; 1.8458x over previous
#include <cuda_runtime.h>
#include <cuda_fp16.h>
#include <cstdint>
#include <math.h>

// ---------------- problem constants ----------------
#define BATCH  2
#define SEQ    2048
#define DMODEL 5120
#define NH     8
#define DHEAD  640
#define DROPE  16
#define SPLITD 624
#define DKV    128
#define BS     (BATCH*SEQ)            // 4096 rows
#define NBASE  (NH*SPLITD)            // 4992
#define NFULL  (NH*DHEAD)             // 5120
#define NDOWN  384                    // ckv | cq | kr
#define NKV    (NBASE + NFULL)        // 10112 : kb | v
#define NQ     (NBASE + 128)          // 5120  : qb | qr

// ---------------- scratch (device globals; no allocations allowed) ----------
__device__ __align__(128) __half g_h16 [(long)BS*DMODEL];
__device__ __align__(128) __half g_cat [(long)BS*NDOWN];    // ckv|cq|kr
__device__ __align__(128) __half g_kv  [(long)BS*NKV];      // kb|v
__device__ __align__(128) __half g_qcat[(long)BS*NQ];       // qb|qr
__device__ __align__(128) __half g_q   [(long)BS*NFULL];
__device__ __align__(128) __half g_k   [(long)BS*NFULL];
__device__ __align__(128) __half g_vT  [(long)BS*NFULL];
__device__ __align__(128) float  g_sc  [(long)BATCH*NH*SEQ*SEQ];  // scores fp32
__device__ __align__(128) __half g_p16 [(long)BATCH*NH*SEQ*SEQ];  // probs fp16
__device__ __align__(128) __half g_ao  [(long)BS*NFULL];
// transposed weights ([N,K] K-major), fp16
__device__ __align__(128) __half g_wDownT[(long)NDOWN*DMODEL];
__device__ __align__(128) __half g_wKvT  [(long)NKV*DKV];
__device__ __align__(128) __half g_wQT   [(long)NQ*DKV];
__device__ __align__(128) __half g_woT   [(long)DMODEL*DMODEL];
// concatenated biases
__device__ __align__(128) float g_bDown[NDOWN];
__device__ __align__(128) float g_bKv  [NKV];
__device__ __align__(128) float g_bQ   [NQ];

// ---------------- helpers ----------------
__device__ __forceinline__ uint32_t smem_to_u32(const void* p) {
    uint32_t a;
    asm("{ .reg .u64 t; cvta.to.shared.u64 t, %1; cvt.u32.u64 %0, t; }" : "=r"(a) : "l"(p));
    return a;
}
__device__ __forceinline__ void cp16(uint32_t dst, const void* src) {
    asm volatile("cp.async.cg.shared.global [%0], [%1], 16;" :: "r"(dst), "l"(src));
}
__device__ __forceinline__ void cp_commit() { asm volatile("cp.async.commit_group;"); }
__device__ __forceinline__ void cp_wait1()  { asm volatile("cp.async.wait_group 1;"); }
__device__ __forceinline__ void cp_wait0()  { asm volatile("cp.async.wait_group 0;"); }

#define MMA_F16(c, a, b) \
    asm volatile("mma.sync.aligned.m16n8k16.row.col.f32.f16.f16.f32 " \
        "{%0,%1,%2,%3}, {%4,%5,%6,%7}, {%8,%9}, {%0,%1,%2,%3};" \
        : "+f"((c)[0]), "+f"((c)[1]), "+f"((c)[2]), "+f"((c)[3]) \
        : "r"((a)[0]), "r"((a)[1]), "r"((a)[2]), "r"((a)[3]), \
          "r"((b)[0]), "r"((b)[1]))

#define LDSM4(r0, r1, r2, r3, addr) \
    asm volatile("ldmatrix.sync.aligned.m8n8.x4.shared.b16 {%0,%1,%2,%3}, [%4];" \
        : "=r"(r0), "=r"(r1), "=r"(r2), "=r"(r3) : "r"(addr))

// =================== fp16 mma.sync NT GEMM, cp.async 3-stage, ldmatrix =======
// C[m,n] = scale * sum_k A[m*lda+k]*B[n*ldb+k] (+ bias[n]).
// A, B fp16; C fp16 (outFloat=0) or fp32 (outFloat=1).
// M%128==0, N%128==0, K%64==0, K>=128.
// CTA 128x128, 256 threads (8 warps, 4M x 2N), warp tile 32x64, KC=64.
// Smem per stage per operand: 128 rows x 64 halves = 16KB, XOR-swizzled:
//   phys_chunk = chunk ^ (row & 7); rows are 128B apart.
#define STG_B 32768                    // bytes per stage (A 16K + B 16K)
#define GEMM_SMEM (3*STG_B)            // 98304

struct CpMap { int row[4]; int ck[4]; };

__device__ __forceinline__ void issue_stage(
    const CpMap& mp, uint32_t sb, int t,
    const __half* Ag, int lda, const __half* Bg, int ldb)
{
    const __half* Ak = Ag + (long)t*64;
    const __half* Bk = Bg + (long)t*64;
    const uint32_t d = sb + (uint32_t)((t % 3) * STG_B);
    #pragma unroll
    for (int i = 0; i < 4; i++) {
        const uint32_t o = (uint32_t)(mp.row[i]*128)
                         + (uint32_t)(((mp.ck[i] ^ (mp.row[i] & 7)) << 4));
        cp16(d + o,           Ak + (long)mp.row[i]*lda + mp.ck[i]*8);
        cp16(d + 16384u + o,  Bk + (long)mp.row[i]*ldb + mp.ck[i]*8);
    }
    cp_commit();
}

__global__ void __launch_bounds__(256, 2) gemm_h(
    int M, int N, int K,
    const __half* __restrict__ A, int lda, long offA_b, long offA_h,
    const __half* __restrict__ B, int ldb, long offB_b, long offB_h,
    void* __restrict__ Cv, int ldc, long offC_b, long offC_h,
    const float* __restrict__ bias, float scale, int nh, int outFloat)
{
    extern __shared__ char smc[];
    const int tid  = threadIdx.x;
    const int wid  = tid >> 5, lane = tid & 31;
    const int g    = lane >> 2, tq = lane & 3;
    const int warpM = wid >> 1, warpN = wid & 1;

    const int z  = blockIdx.z;
    const int bz = z / nh, hz = z - bz*nh;
    A += (long)bz*offA_b + (long)hz*offA_h;
    B += (long)bz*offB_b + (long)hz*offB_h;

    const int mBase = blockIdx.y * 128;
    const int nBase = blockIdx.x * 128;
    const __half* Ag = A + (long)mBase*lda;
    const __half* Bg = B + (long)nBase*ldb;
    const uint32_t sb = smem_to_u32(smc);

    CpMap mp;
    #pragma unroll
    for (int i = 0; i < 4; i++) {
        int f = i*256 + tid;
        mp.row[i] = f >> 3;
        mp.ck[i]  = f & 7;
    }

    // ldmatrix per-thread row/chunk bases (within tile)
    const int aRow = warpM*32 + (lane & 15);      // + mt*16
    const int aCk  = lane >> 4;                   // + ks*2
    const int bRow = warpN*64 + ((lane >> 4) << 3) + (lane & 7);  // + p*16
    const int bCk  = (lane >> 3) & 1;             // + ks*2

    float acc[2][8][4];
    #pragma unroll
    for (int mt = 0; mt < 2; mt++)
        #pragma unroll
        for (int nt = 0; nt < 8; nt++)
            #pragma unroll
            for (int r = 0; r < 4; r++) acc[mt][nt][r] = 0.f;

    const int T = K / 64;

    issue_stage(mp, sb, 0, Ag, lda, Bg, ldb);
    issue_stage(mp, sb, 1, Ag, lda, Bg, ldb);

    for (int t = 0; t < T; ++t) {
        if (t == T-1) cp_wait0(); else cp_wait1();
        __syncthreads();
        if (t + 2 < T) issue_stage(mp, sb, t+2, Ag, lda, Bg, ldb);

        const uint32_t sA = sb + (uint32_t)((t % 3)*STG_B);
        const uint32_t sB = sA + 16384u;
        #pragma unroll
        for (int ks = 0; ks < 4; ks++) {
            uint32_t afr[2][4], bfr[8][2];
            #pragma unroll
            for (int mt = 0; mt < 2; mt++) {
                const int row = aRow + mt*16;
                const int ck  = ks*2 + aCk;
                const uint32_t ad = sA + (uint32_t)(row*128) + (uint32_t)(((ck ^ (row & 7)) << 4));
                LDSM4(afr[mt][0], afr[mt][1], afr[mt][2], afr[mt][3], ad);
            }
            #pragma unroll
            for (int p = 0; p < 4; p++) {
                const int row = bRow + p*16;
                const int ck  = ks*2 + bCk;
                const uint32_t ad = sB + (uint32_t)(row*128) + (uint32_t)(((ck ^ (row & 7)) << 4));
                LDSM4(bfr[2*p][0], bfr[2*p][1], bfr[2*p+1][0], bfr[2*p+1][1], ad);
            }
            #pragma unroll
            for (int mt = 0; mt < 2; mt++)
                #pragma unroll
                for (int nt = 0; nt < 8; nt++)
                    MMA_F16(acc[mt][nt], afr[mt], bfr[nt]);
        }
    }

    // epilogue
    #pragma unroll
    for (int mt = 0; mt < 2; mt++) {
        const int m0 = mBase + warpM*32 + mt*16 + g;
        #pragma unroll
        for (int nt = 0; nt < 8; nt++) {
            const int nc = nBase + warpN*64 + nt*8 + 2*tq;
            float ax = acc[mt][nt][0]*scale, ay = acc[mt][nt][1]*scale;
            float bx = acc[mt][nt][2]*scale, by = acc[mt][nt][3]*scale;
            if (bias) {
                float u = bias[nc], w = bias[nc+1];
                ax += u; ay += w; bx += u; by += w;
            }
            if (outFloat) {
                float* C = (float*)Cv + (long)bz*offC_b + (long)hz*offC_h;
                *(float2*)(C + (long)m0*ldc + nc)     = make_float2(ax, ay);
                *(float2*)(C + (long)(m0+8)*ldc + nc) = make_float2(bx, by);
            } else {
                __half* C = (__half*)Cv + (long)bz*offC_b + (long)hz*offC_h;
                *(__half2*)(C + (long)m0*ldc + nc)     = __floats2half2_rn(ax, ay);
                *(__half2*)(C + (long)(m0+8)*ldc + nc) = __floats2half2_rn(bx, by);
            }
        }
    }
}

// ---------------- h (fp32) -> fp16 ----------------
__global__ void __launch_bounds__(256) round_h(
    const float* __restrict__ in, __half* __restrict__ out, long n4)
{
    long i = (long)blockIdx.x * blockDim.x + threadIdx.x;
    if (i >= n4) return;
    float4 v = ((const float4*)in)[i];
    ((__half2*)out)[2*i]   = __floats2half2_rn(v.x, v.y);
    ((__half2*)out)[2*i+1] = __floats2half2_rn(v.z, v.w);
}

// ---------------- concat biases ----------------
__global__ void __launch_bounds__(256) concat_bias(
    const float* __restrict__ b_dkv, const float* __restrict__ b_dq,
    const float* __restrict__ b_kr,  const float* __restrict__ b_uk,
    const float* __restrict__ b_uv,  const float* __restrict__ b_uq,
    const float* __restrict__ b_qr,
    float* __restrict__ bDown, float* __restrict__ bKv, float* __restrict__ bQ)
{
    int i = blockIdx.x*blockDim.x + threadIdx.x;
    if (i < 128) {
        bDown[i] = b_dkv[i]; bDown[128+i] = b_dq[i]; bDown[256+i] = b_kr[i];
        bQ[NBASE+i] = b_qr[i];
    }
    if (i < NBASE) { bKv[i] = b_uk[i]; bQ[i] = b_uq[i]; }
    if (i < NFULL) bKv[NBASE+i] = b_uv[i];
}

// =================== transposes ===================
// weights: float in [R,C] -> half out [C,R] (out may point into a concat buffer)
__global__ void __launch_bounds__(256) transpose_w(
    const float* __restrict__ in, int ldin,
    __half* __restrict__ out, int ldout, int R, int Ccols)
{
    __shared__ float tile[32][33];
    const int tx = threadIdx.x & 31, ty = threadIdx.x >> 5;
    const int bx = blockIdx.x * 32, by = blockIdx.y * 32;
    #pragma unroll
    for (int j = ty; j < 32; j += 8) {
        int r = by + j, c = bx + tx;
        if (r < R && c < Ccols) tile[j][tx] = in[(long)r*ldin + c];
    }
    __syncthreads();
    #pragma unroll
    for (int j = ty; j < 32; j += 8) {
        int r = bx + j, c = by + tx;
        if (r < Ccols && c < R) out[(long)r*ldout + c] = __float2half_rn(tile[tx][j]);
    }
}

// kv[b, s, NBASE + h*640 + d] -> vT[(b*NH+h), d, s]
__global__ void __launch_bounds__(256) transpose_v(
    const __half* __restrict__ kv, __half* __restrict__ vT)
{
    __shared__ __half tile[32][34];
    const int z = blockIdx.z;
    const int b = z >> 3, h = z & 7;
    const __half* in = kv + (long)b*SEQ*NKV + NBASE + h*DHEAD;
    __half* out = vT + (long)z*DHEAD*SEQ;
    const int tx = threadIdx.x & 31, ty = threadIdx.x >> 5;
    const int bx = blockIdx.x * 32;   // d
    const int by = blockIdx.y * 32;   // s
    #pragma unroll
    for (int j = ty; j < 32; j += 8)
        tile[j][tx] = in[(long)(by + j)*NKV + bx + tx];
    __syncthreads();
    #pragma unroll
    for (int j = ty; j < 32; j += 8)
        out[(long)(bx + j)*SEQ + by + tx] = tile[tx][j];
}

// ---------------- pack q/k (concat base + rotated rope), fp16 ----------------
// qcat[bs, NQ]: qb cols 0..4991, qr cols 4992..5119 (h*16 each)
// kv  [bs, NKV]: kb cols 0..4991
// cat [bs, NDOWN]: kr cols 256..383 (h*16 each)
__global__ void __launch_bounds__(256) pack_rope(
    const __half* __restrict__ qcat, const __half* __restrict__ kv,
    const __half* __restrict__ cat,
    __half* __restrict__ q, __half* __restrict__ k)
{
    long idx = (long)blockIdx.x * blockDim.x + threadIdx.x;
    const long total = (long)BS * NH * DHEAD;
    if (idx >= total) return;
    int d  = (int)(idx % DHEAD);
    int hh = (int)((idx / DHEAD) % NH);
    long bs = idx / ((long)DHEAD * NH);
    float qv, kv_;
    if (d < SPLITD) {
        qv  = __half2float(qcat[bs*NQ  + hh*SPLITD + d]);
        kv_ = __half2float(kv  [bs*NKV + hh*SPLITD + d]);
    } else {
        int i = d - SPLITD;   // 0..15
        const __half* qr = qcat + bs*NQ + NBASE + hh*DROPE;
        const __half* kr = cat + bs*NDOWN + 256 + hh*DROPE;
        if (i < 8) {
            int s = (int)(bs % SEQ);
            int j = i & 3;
            float invf = (j == 0) ? 1.f : (j == 1) ? 0.1f : (j == 2) ? 0.01f : 0.001f;
            float ang = ((float)s / 40.0f) * invf;
            float c = cosf(ang), sn = sinf(ang);
            if (i < 4) {
                qv  = __half2float(qr[i])*c - __half2float(qr[i+4])*sn;
                kv_ = __half2float(kr[i])*c - __half2float(kr[i+4])*sn;
            } else {
                qv  = __half2float(qr[i])*c + __half2float(qr[i-4])*sn;
                kv_ = __half2float(kr[i])*c + __half2float(kr[i-4])*sn;
            }
        } else {
            qv = __half2float(qr[i]); kv_ = __half2float(kr[i]);
        }
    }
    q[idx] = __float2half_rn(qv); k[idx] = __float2half_rn(kv_);
}

// ---------------- softmax: fp32 scores in, fp16 probs out --------------------
__device__ __forceinline__ float warpMax(float v){
    #pragma unroll
    for (int o = 16; o; o >>= 1) v = fmaxf(v, __shfl_xor_sync(0xffffffffu, v, o));
    return v;
}
__device__ __forceinline__ float warpSum(float v){
    #pragma unroll
    for (int o = 16; o; o >>= 1) v += __shfl_xor_sync(0xffffffffu, v, o);
    return v;
}

__global__ void __launch_bounds__(256) softmax_rows(
    const float* __restrict__ sc, __half* __restrict__ p)
{
    const float* row = sc + (long)blockIdx.x * SEQ;
    __half* prow = p + (long)blockIdx.x * SEQ;
    const int t = threadIdx.x;
    float4 a = *(const float4*)(row + 4*t);
    float4 b = *(const float4*)(row + 1024 + 4*t);

    float m = fmaxf(fmaxf(fmaxf(a.x, a.y), fmaxf(a.z, a.w)),
                    fmaxf(fmaxf(b.x, b.y), fmaxf(b.z, b.w)));
    __shared__ float sm[8], ss[8];
    float wm = warpMax(m);
    if ((t & 31) == 0) sm[t >> 5] = wm;
    __syncthreads();
    if (t < 32) { float x = (t < 8) ? sm[t] : -INFINITY; x = warpMax(x); if (t == 0) sm[0] = x; }
    __syncthreads();
    const float bm = sm[0];

    a.x = __expf(a.x - bm); a.y = __expf(a.y - bm); a.z = __expf(a.z - bm); a.w = __expf(a.w - bm);
    b.x = __expf(b.x - bm); b.y = __expf(b.y - bm); b.z = __expf(b.z - bm); b.w = __expf(b.w - bm);
    float s = a.x + a.y + a.z + a.w + b.x + b.y + b.z + b.w;
    float wsu = warpSum(s);
    if ((t & 31) == 0) ss[t >> 5] = wsu;
    __syncthreads();
    if (t < 32) { float x = (t < 8) ? ss[t] : 0.f; x = warpSum(x); if (t == 0) ss[0] = x; }
    __syncthreads();
    const float inv = 1.f / ss[0];

    *(__half2*)(prow + 4*t)          = __floats2half2_rn(a.x*inv, a.y*inv);
    *(__half2*)(prow + 4*t + 2)      = __floats2half2_rn(a.z*inv, a.w*inv);
    *(__half2*)(prow + 1024 + 4*t)   = __floats2half2_rn(b.x*inv, b.y*inv);
    *(__half2*)(prow + 1024 + 4*t+2) = __floats2half2_rn(b.z*inv, b.w*inv);
}

// ---------------- launch ------------------------------------------------------
extern "C" void kernel_launch(void* const* d_in, const int* in_sizes, int n_in,
                              void* d_out, int out_size)
{
    const float* h     = (const float*)d_in[0];
    const float* W_dkv = (const float*)d_in[1];
    const float* b_dkv = (const float*)d_in[2];
    const float* W_dq  = (const float*)d_in[3];
    const float* b_dq  = (const float*)d_in[4];
    const float* W_uk  = (const float*)d_in[5];
    const float* b_uk  = (const float*)d_in[6];
    const float* W_uv  = (const float*)d_in[7];
    const float* b_uv  = (const float*)d_in[8];
    const float* W_uq  = (const float*)d_in[9];
    const float* b_uq  = (const float*)d_in[10];
    const float* W_qr  = (const float*)d_in[11];
    const float* b_qr  = (const float*)d_in[12];
    const float* W_kr  = (const float*)d_in[13];
    const float* b_kr  = (const float*)d_in[14];
    const float* W_o   = (const float*)d_in[15];
    const float* b_o   = (const float*)d_in[16];
    float* out = (float*)d_out;

    __half *h16, *cat, *kvb, *qcat, *q, *k, *vT, *p16, *ao;
    __half *wDownT, *wKvT, *wQT, *woT;
    float *sc, *bDown, *bKv, *bQ;
    cudaGetSymbolAddress((void**)&h16,  g_h16);
    cudaGetSymbolAddress((void**)&cat,  g_cat);
    cudaGetSymbolAddress((void**)&kvb,  g_kv);
    cudaGetSymbolAddress((void**)&qcat, g_qcat);
    cudaGetSymbolAddress((void**)&q,    g_q);
    cudaGetSymbolAddress((void**)&k,    g_k);
    cudaGetSymbolAddress((void**)&vT,   g_vT);
    cudaGetSymbolAddress((void**)&sc,   g_sc);
    cudaGetSymbolAddress((void**)&p16,  g_p16);
    cudaGetSymbolAddress((void**)&ao,   g_ao);
    cudaGetSymbolAddress((void**)&wDownT, g_wDownT);
    cudaGetSymbolAddress((void**)&wKvT,   g_wKvT);
    cudaGetSymbolAddress((void**)&wQT,    g_wQT);
    cudaGetSymbolAddress((void**)&woT,    g_woT);
    cudaGetSymbolAddress((void**)&bDown,  g_bDown);
    cudaGetSymbolAddress((void**)&bKv,    g_bKv);
    cudaGetSymbolAddress((void**)&bQ,     g_bQ);

    cudaFuncSetAttribute(gemm_h, cudaFuncAttributeMaxDynamicSharedMemorySize, GEMM_SMEM);

    const dim3 T256(256);
    const long SS  = (long)SEQ * SEQ;
    const long ROW = (long)SEQ * NFULL;

    // #1: h -> fp16
    {
        long n4 = ((long)BS * DMODEL) / 4;
        round_h<<<(int)((n4 + 255) / 256), T256>>>(h, h16, n4);
    }
    // #2-4: down weights -> wDownT rows [0,128) dkv, [128,256) dq, [256,384) kr
    transpose_w<<<dim3(DKV/32, DMODEL/32), T256>>>(W_dkv, DKV, wDownT, DMODEL, DMODEL, DKV);
    transpose_w<<<dim3(DKV/32, DMODEL/32), T256>>>(W_dq,  DKV, wDownT + (long)128*DMODEL, DMODEL, DMODEL, DKV);
    transpose_w<<<dim3(DKV/32, DMODEL/32), T256>>>(W_kr,  DKV, wDownT + (long)256*DMODEL, DMODEL, DMODEL, DKV);
    // #5: biases
    concat_bias<<<dim3((NFULL + 255)/256), T256>>>(b_dkv, b_dq, b_kr, b_uk, b_uv, b_uq, b_qr,
                                                   bDown, bKv, bQ);
    // #6 (ncu lands here): fused down GEMM cat = h @ [W_dkv|W_dq|W_kr]^T  (N=384)
    gemm_h<<<dim3(NDOWN/128, BS/128, 1), T256, GEMM_SMEM>>>(BS, NDOWN, DMODEL,
        h16, DMODEL, 0, 0, wDownT, DMODEL, 0, 0, cat, NDOWN, 0, 0, bDown, 1.f, 1, 0);

    // up-proj weights: wKvT rows [0,4992) uk, [4992,10112) uv; wQT rows [0,4992) uq, [4992,5120) qr
    transpose_w<<<dim3(NBASE/32, DKV/32), T256>>>(W_uk, NBASE, wKvT, DKV, DKV, NBASE);
    transpose_w<<<dim3(NFULL/32, DKV/32), T256>>>(W_uv, NFULL, wKvT + (long)NBASE*DKV, DKV, DKV, NFULL);
    transpose_w<<<dim3(NBASE/32, DKV/32), T256>>>(W_uq, NBASE, wQT, DKV, DKV, NBASE);
    transpose_w<<<dim3((128)/32, DKV/32), T256>>>(W_qr, 128, wQT + (long)NBASE*DKV, DKV, DKV, 128);

    // fused up-projections (K=128)
    gemm_h<<<dim3(NKV/128, BS/128, 1), T256, GEMM_SMEM>>>(BS, NKV, DKV,
        cat, NDOWN, 0, 0, wKvT, DKV, 0, 0, kvb, NKV, 0, 0, bKv, 1.f, 1, 0);
    gemm_h<<<dim3(NQ/128, BS/128, 1), T256, GEMM_SMEM>>>(BS, NQ, DKV,
        cat + 128, NDOWN, 0, 0, wQT, DKV, 0, 0, qcat, NQ, 0, 0, bQ, 1.f, 1, 0);

    // pack q/k + RoPE; transpose v per head
    {
        long total = (long)BS * NH * DHEAD;
        pack_rope<<<(int)((total + 255) / 256), T256>>>(qcat, kvb, cat, q, k);
    }
    transpose_v<<<dim3(DHEAD/32, SEQ/32, BATCH*NH), T256>>>(kvb, vT);

    // scores = q @ k^T / sqrt(D_HEAD) -> fp32
    const float scScale = 1.f / sqrtf((float)DHEAD);
    gemm_h<<<dim3(SEQ/128, SEQ/128, BATCH*NH), T256, GEMM_SMEM>>>(SEQ, SEQ, DHEAD,
        q, NFULL, ROW, DHEAD,
        k, NFULL, ROW, DHEAD,
        sc, SEQ, (long)NH*SS, SS,
        (const float*)nullptr, scScale, NH, 1);

    // softmax -> fp16 probs
    softmax_rows<<<BATCH*NH*SEQ, T256>>>(sc, p16);

    // ao = attn @ v
    gemm_h<<<dim3(DHEAD/128, SEQ/128, BATCH*NH), T256, GEMM_SMEM>>>(SEQ, DHEAD, SEQ,
        p16, SEQ, (long)NH*SS, SS,
        vT, SEQ, (long)NH*DHEAD*SEQ, (long)DHEAD*SEQ,
        ao, NFULL, ROW, DHEAD,
        (const float*)nullptr, 1.f, NH, 0);

    // final projection -> fp32 out
    transpose_w<<<dim3(DMODEL/32, DMODEL/32), T256>>>(W_o, DMODEL, woT, DMODEL, DMODEL, DMODEL);
    gemm_h<<<dim3(DMODEL/128, BS/128, 1), T256, GEMM_SMEM>>>(BS, DMODEL, DMODEL,
        ao, DMODEL, 0, 0, woT, DMODEL, 0, 0, out, DMODEL, 0, 0, b_o, 1.f, 1, 1);
}